// round 1
// baseline (speedup 1.0000x reference)
#include <cuda_runtime.h>
#include <cuda_bf16.h>

#define B_   64
#define N_   1000
#define F_   64
#define E_   32000
#define IND  64000          // N_*F_
#define HID  512
#define L_   128
#define KSTEP 32
#define ENC_SPLITK 100
#define ENC_CHUNK  640      // 64000 / 100

// ---------------- scratch (device globals; no allocations allowed) ----------
__device__ int   g_deg[N_];
__device__ int   g_fill[N_];
__device__ int   g_rowptr[N_ + 1];
__device__ int   g_col[E_];
__device__ float g_xs[B_ * IND];     // conv output, reshaped [B, 64000]
__device__ float g_acc[B_ * HID];    // encoder split-K accumulator
__device__ float g_he[B_ * HID];
__device__ float g_z[B_ * L_];
__device__ float g_hd[B_ * HID];

// ---------------- helpers ---------------------------------------------------
__device__ __forceinline__ unsigned f2tf32(float f) {
    unsigned r;
    asm("cvt.rna.tf32.f32 %0, %1;" : "=r"(r) : "f"(f));
    return r;
}

__device__ __forceinline__ void mma_tf32(float c[4],
                                         unsigned a0, unsigned a1, unsigned a2, unsigned a3,
                                         unsigned b0, unsigned b1) {
    asm volatile(
        "mma.sync.aligned.m16n8k8.row.col.f32.tf32.tf32.f32 "
        "{%0,%1,%2,%3}, {%4,%5,%6,%7}, {%8,%9}, {%0,%1,%2,%3};"
        : "+f"(c[0]), "+f"(c[1]), "+f"(c[2]), "+f"(c[3])
        : "r"(a0), "r"(a1), "r"(a2), "r"(a3), "r"(b0), "r"(b1));
}

// ---------------- CSR build --------------------------------------------------
__global__ void k_init() {
    int i = blockIdx.x * blockDim.x + threadIdx.x;
    if (i < N_) { g_deg[i] = 0; g_fill[i] = 0; }
    if (i < B_ * HID) g_acc[i] = 0.f;
}

__global__ void k_count(const int* __restrict__ ei) {
    int e = blockIdx.x * blockDim.x + threadIdx.x;
    if (e < E_) atomicAdd(&g_deg[ei[E_ + e]], 1);
}

__global__ void k_scan() {
    __shared__ int sh[1024];
    int t = threadIdx.x;
    sh[t] = (t < N_) ? g_deg[t] : 0;
    __syncthreads();
    for (int off = 1; off < 1024; off <<= 1) {
        int v = (t >= off) ? sh[t - off] : 0;
        __syncthreads();
        sh[t] += v;
        __syncthreads();
    }
    if (t < N_) g_rowptr[t + 1] = sh[t];
    if (t == 0) g_rowptr[0] = 0;
}

__global__ void k_fill(const int* __restrict__ ei) {
    int e = blockIdx.x * blockDim.x + threadIdx.x;
    if (e < E_) {
        int d = ei[E_ + e];
        int p = atomicAdd(&g_fill[d], 1);
        g_col[g_rowptr[d] + p] = ei[e];
    }
}

// ---------------- fused GeneralConv (gather-sum -> W_msg -> skip -> leaky) ---
__global__ void __launch_bounds__(256) k_conv(const float* __restrict__ x,
                                              const float* __restrict__ Wm,
                                              const float* __restrict__ bm) {
    __shared__ float Wsh[F_ * F_];
    __shared__ float accsh[4][F_ + 4];
    int n = blockIdx.x;
    int t = threadIdx.x;
    for (int i = t; i < F_ * F_; i += 256) Wsh[i] = Wm[i];
    int r0 = g_rowptr[n], r1 = g_rowptr[n + 1];
    int deg = r1 - r0;
    float inv = 1.f / fmaxf((float)deg, 1.f);
    int bl = t >> 6;
    int f  = t & 63;
    float bias = (deg > 0) ? bm[f] : 0.f;
    __syncthreads();
    for (int bc = 0; bc < 16; ++bc) {
        int b = bc * 4 + bl;
        float a = 0.f;
        #pragma unroll 4
        for (int j = r0; j < r1; ++j) {
            int s = g_col[j];
            a += x[(b * N_ + s) * F_ + f];
        }
        accsh[bl][f] = a;
        __syncthreads();
        float v = 0.f;
        #pragma unroll
        for (int k = 0; k < F_; ++k) v += accsh[bl][k] * Wsh[k * F_ + f];
        v = v * inv + bias;
        float h = v + x[(b * N_ + n) * F_ + f];
        h = (h >= 0.f) ? h : 0.01f * h;
        g_xs[(b * N_ + n) * F_ + f] = h;
        __syncthreads();
    }
}

// ---------------- encoder GEMM: [64,64000] @ [64000,512], tf32, split-K ------
__global__ void __launch_bounds__(256) k_gemm_enc(const float* __restrict__ W) {
    __shared__ float Ash[64][KSTEP + 4];     // [m][k]
    __shared__ float Bsh[KSTEP][128 + 4];    // [k][n]
    int nblk = blockIdx.x;                   // 0..3  (128-wide N tiles)
    int kblk = blockIdx.y;                   // 0..99
    int t = threadIdx.x;
    int warp = t >> 5, lane = t & 31;
    int gid = lane >> 2, tid4 = lane & 3;
    int m0 = (warp & 3) * 16;
    int nb = (warp >> 2) * 64;
    float acc[8][4];
    #pragma unroll
    for (int i = 0; i < 8; i++)
        #pragma unroll
        for (int j = 0; j < 4; j++) acc[i][j] = 0.f;

    int kbase0 = kblk * ENC_CHUNK;
    for (int kt = 0; kt < ENC_CHUNK; kt += KSTEP) {
        int kbase = kbase0 + kt;
        {   // A: 64 x 32, thread loads 2x float4
            int m = t >> 2, kk = (t & 3) * 8;
            const float4* s4 = reinterpret_cast<const float4*>(&g_xs[m * IND + kbase + kk]);
            float4 v0 = s4[0], v1 = s4[1];
            Ash[m][kk + 0] = v0.x; Ash[m][kk + 1] = v0.y; Ash[m][kk + 2] = v0.z; Ash[m][kk + 3] = v0.w;
            Ash[m][kk + 4] = v1.x; Ash[m][kk + 5] = v1.y; Ash[m][kk + 6] = v1.z; Ash[m][kk + 7] = v1.w;
        }
        {   // B: 32 x 128, thread loads 4x float4
            int k = t >> 3, jj = (t & 7) * 16;
            const float4* s4 = reinterpret_cast<const float4*>(&W[(kbase + k) * HID + nblk * 128 + jj]);
            #pragma unroll
            for (int q = 0; q < 4; q++) {
                float4 v = s4[q];
                Bsh[k][jj + q * 4 + 0] = v.x; Bsh[k][jj + q * 4 + 1] = v.y;
                Bsh[k][jj + q * 4 + 2] = v.z; Bsh[k][jj + q * 4 + 3] = v.w;
            }
        }
        __syncthreads();
        #pragma unroll
        for (int kk = 0; kk < KSTEP; kk += 8) {
            unsigned a0 = f2tf32(Ash[m0 + gid][kk + tid4]);
            unsigned a1 = f2tf32(Ash[m0 + gid + 8][kk + tid4]);
            unsigned a2 = f2tf32(Ash[m0 + gid][kk + tid4 + 4]);
            unsigned a3 = f2tf32(Ash[m0 + gid + 8][kk + tid4 + 4]);
            #pragma unroll
            for (int nt = 0; nt < 8; nt++) {
                int nn = nb + nt * 8 + gid;
                unsigned b0 = f2tf32(Bsh[kk + tid4][nn]);
                unsigned b1 = f2tf32(Bsh[kk + tid4 + 4][nn]);
                mma_tf32(acc[nt], a0, a1, a2, a3, b0, b1);
            }
        }
        __syncthreads();
    }
    #pragma unroll
    for (int nt = 0; nt < 8; nt++) {
        int nn = nblk * 128 + nb + nt * 8 + tid4 * 2;
        int m = m0 + gid;
        atomicAdd(&g_acc[m * HID + nn],           acc[nt][0]);
        atomicAdd(&g_acc[m * HID + nn + 1],       acc[nt][1]);
        atomicAdd(&g_acc[(m + 8) * HID + nn],     acc[nt][2]);
        atomicAdd(&g_acc[(m + 8) * HID + nn + 1], acc[nt][3]);
    }
}

__global__ void k_enc_epi(const float* __restrict__ b_e1) {
    int i = blockIdx.x * blockDim.x + threadIdx.x;
    if (i < B_ * HID) g_he[i] = fmaxf(g_acc[i] + b_e1[i & (HID - 1)], 0.f);
}

// ---------------- mean / log_var / reparameterize ----------------------------
__global__ void k_small1(const float* __restrict__ Wmean, const float* __restrict__ bmean,
                         const float* __restrict__ Wlv,   const float* __restrict__ blv,
                         const float* __restrict__ eps,
                         float* __restrict__ out_mean, float* __restrict__ out_lv) {
    __shared__ float hesh[HID];
    int b = blockIdx.x, l = threadIdx.x;
    for (int i = l; i < HID; i += 128) hesh[i] = g_he[b * HID + i];
    __syncthreads();
    float m = 0.f, v = 0.f;
    #pragma unroll 8
    for (int k = 0; k < HID; ++k) {
        float h = hesh[k];
        m += h * Wmean[k * L_ + l];
        v += h * Wlv[k * L_ + l];
    }
    m += bmean[l]; v += blv[l];
    out_mean[b * L_ + l] = m;
    out_lv[b * L_ + l]   = v;
    g_z[b * L_ + l] = m + expf(0.5f * v) * eps[b * L_ + l];
}

// ---------------- hd = relu(z @ W_d1 + b_d1) ---------------------------------
__global__ void k_small2(const float* __restrict__ Wd1, const float* __restrict__ bd1) {
    __shared__ float zsh[L_];
    int b = blockIdx.x, t = threadIdx.x;
    if (t < L_) zsh[t] = g_z[b * L_ + t];
    __syncthreads();
    float a = 0.f;
    #pragma unroll 8
    for (int k = 0; k < L_; ++k) a += zsh[k] * Wd1[k * HID + t];
    g_hd[b * HID + t] = fmaxf(a + bd1[t], 0.f);
}

// ---------------- decoder GEMM: [64,512] @ [512,64000] + sigmoid -------------
__global__ void __launch_bounds__(256) k_gemm_dec(const float* __restrict__ W,
                                                  const float* __restrict__ bd2,
                                                  float* __restrict__ out) {
    __shared__ float Ash[64][KSTEP + 4];
    __shared__ float Bsh[KSTEP][128 + 4];
    int nblk = blockIdx.x;                   // 0..499
    int t = threadIdx.x;
    int warp = t >> 5, lane = t & 31;
    int gid = lane >> 2, tid4 = lane & 3;
    int m0 = (warp & 3) * 16;
    int nb = (warp >> 2) * 64;
    float acc[8][4];
    #pragma unroll
    for (int i = 0; i < 8; i++)
        #pragma unroll
        for (int j = 0; j < 4; j++) acc[i][j] = 0.f;

    for (int kbase = 0; kbase < HID; kbase += KSTEP) {
        {
            int m = t >> 2, kk = (t & 3) * 8;
            const float4* s4 = reinterpret_cast<const float4*>(&g_hd[m * HID + kbase + kk]);
            float4 v0 = s4[0], v1 = s4[1];
            Ash[m][kk + 0] = v0.x; Ash[m][kk + 1] = v0.y; Ash[m][kk + 2] = v0.z; Ash[m][kk + 3] = v0.w;
            Ash[m][kk + 4] = v1.x; Ash[m][kk + 5] = v1.y; Ash[m][kk + 6] = v1.z; Ash[m][kk + 7] = v1.w;
        }
        {
            int k = t >> 3, jj = (t & 7) * 16;
            const float4* s4 = reinterpret_cast<const float4*>(&W[(kbase + k) * IND + nblk * 128 + jj]);
            #pragma unroll
            for (int q = 0; q < 4; q++) {
                float4 v = s4[q];
                Bsh[k][jj + q * 4 + 0] = v.x; Bsh[k][jj + q * 4 + 1] = v.y;
                Bsh[k][jj + q * 4 + 2] = v.z; Bsh[k][jj + q * 4 + 3] = v.w;
            }
        }
        __syncthreads();
        #pragma unroll
        for (int kk = 0; kk < KSTEP; kk += 8) {
            unsigned a0 = f2tf32(Ash[m0 + gid][kk + tid4]);
            unsigned a1 = f2tf32(Ash[m0 + gid + 8][kk + tid4]);
            unsigned a2 = f2tf32(Ash[m0 + gid][kk + tid4 + 4]);
            unsigned a3 = f2tf32(Ash[m0 + gid + 8][kk + tid4 + 4]);
            #pragma unroll
            for (int nt = 0; nt < 8; nt++) {
                int nn = nb + nt * 8 + gid;
                unsigned b0 = f2tf32(Bsh[kk + tid4][nn]);
                unsigned b1 = f2tf32(Bsh[kk + tid4 + 4][nn]);
                mma_tf32(acc[nt], a0, a1, a2, a3, b0, b1);
            }
        }
        __syncthreads();
    }
    #pragma unroll
    for (int nt = 0; nt < 8; nt++) {
        int nn = nblk * 128 + nb + nt * 8 + tid4 * 2;
        int m = m0 + gid;
        float bb0 = bd2[nn], bb1 = bd2[nn + 1];
        float v0 = acc[nt][0] + bb0, v1 = acc[nt][1] + bb1;
        float v2 = acc[nt][2] + bb0, v3 = acc[nt][3] + bb1;
        out[m * IND + nn]           = 1.f / (1.f + __expf(-v0));
        out[m * IND + nn + 1]       = 1.f / (1.f + __expf(-v1));
        out[(m + 8) * IND + nn]     = 1.f / (1.f + __expf(-v2));
        out[(m + 8) * IND + nn + 1] = 1.f / (1.f + __expf(-v3));
    }
}

// ---------------- launch -----------------------------------------------------
extern "C" void kernel_launch(void* const* d_in, const int* in_sizes, int n_in,
                              void* d_out, int out_size) {
    const float* x      = (const float*)d_in[0];
    const int*   ei     = (const int*)d_in[1];
    const float* eps    = (const float*)d_in[2];
    const float* Wmsg   = (const float*)d_in[3];
    const float* bmsg   = (const float*)d_in[4];
    const float* We1    = (const float*)d_in[5];
    const float* be1    = (const float*)d_in[6];
    const float* Wmean  = (const float*)d_in[7];
    const float* bmean  = (const float*)d_in[8];
    const float* Wlv    = (const float*)d_in[9];
    const float* blv    = (const float*)d_in[10];
    const float* Wd1    = (const float*)d_in[11];
    const float* bd1    = (const float*)d_in[12];
    const float* Wd2    = (const float*)d_in[13];
    const float* bd2    = (const float*)d_in[14];

    float* out      = (float*)d_out;
    float* out_xhat = out;
    float* out_mean = out + (size_t)B_ * IND;
    float* out_lv   = out_mean + B_ * L_;

    k_init<<<(B_ * HID + 255) / 256, 256>>>();
    k_count<<<(E_ + 255) / 256, 256>>>(ei);
    k_scan<<<1, 1024>>>();
    k_fill<<<(E_ + 255) / 256, 256>>>(ei);
    k_conv<<<N_, 256>>>(x, Wmsg, bmsg);
    k_gemm_enc<<<dim3(4, ENC_SPLITK), 256>>>(We1);
    k_enc_epi<<<(B_ * HID + 255) / 256, 256>>>(be1);
    k_small1<<<B_, 128>>>(Wmean, bmean, Wlv, blv, eps, out_mean, out_lv);
    k_small2<<<B_, HID>>>(Wd1, bd1);
    k_gemm_dec<<<IND / 128, 256>>>(Wd2, bd2, out_xhat);
}

// round 2
// speedup vs baseline: 1.5097x; 1.5097x over previous
#include <cuda_runtime.h>

#define B_   64
#define N_   1000
#define F_   64
#define E_   32000
#define IND  64000
#define HID  512
#define L_   128
#define ENC_KBLK 100
#define ENC_TILES 20     // k-tiles of 32 per encoder block (20*32*100 = 64000)
#define DEC_TILES 16     // 512 / 32

// ---------------- scratch ----------------------------------------------------
__device__ int   g_deg[N_];
__device__ int   g_fill[N_];
__device__ int   g_rowptr[N_ + 1];
__device__ int   g_col[E_];
__device__ float g_xs[B_ * IND];
__device__ float g_part[ENC_KBLK * B_ * HID];   // 13.1 MB split-K partials
__device__ float g_he[B_ * HID];
__device__ float g_hd[B_ * HID];

// ---------------- helpers ----------------------------------------------------
__device__ __forceinline__ unsigned f2tf32(float f) {
    unsigned r;
    asm("cvt.rna.tf32.f32 %0, %1;" : "=r"(r) : "f"(f));
    return r;
}

__device__ __forceinline__ void mma_tf32(float c[4],
                                         unsigned a0, unsigned a1, unsigned a2, unsigned a3,
                                         unsigned b0, unsigned b1) {
    asm volatile(
        "mma.sync.aligned.m16n8k8.row.col.f32.tf32.tf32.f32 "
        "{%0,%1,%2,%3}, {%4,%5,%6,%7}, {%8,%9}, {%0,%1,%2,%3};"
        : "+f"(c[0]), "+f"(c[1]), "+f"(c[2]), "+f"(c[3])
        : "r"(a0), "r"(a1), "r"(a2), "r"(a3), "r"(b0), "r"(b1));
}

// ---------------- CSR build --------------------------------------------------
__global__ void k_init() {
    int t = threadIdx.x;
    if (t < N_) { g_deg[t] = 0; g_fill[t] = 0; }
}

__global__ void k_count(const int* __restrict__ ei) {
    __shared__ int hist[N_];
    int t = threadIdx.x;
    if (t < N_) hist[t] = 0;
    __syncthreads();
    if (t < 1000) {
        int e = blockIdx.x * 1000 + t;
        atomicAdd(&hist[ei[E_ + e]], 1);
    }
    __syncthreads();
    if (t < N_ && hist[t]) atomicAdd(&g_deg[t], hist[t]);
}

__global__ void k_scan() {
    __shared__ int sh[1024];
    int t = threadIdx.x;
    sh[t] = (t < N_) ? g_deg[t] : 0;
    __syncthreads();
    for (int off = 1; off < 1024; off <<= 1) {
        int v = (t >= off) ? sh[t - off] : 0;
        __syncthreads();
        sh[t] += v;
        __syncthreads();
    }
    if (t < N_) g_rowptr[t + 1] = sh[t];
    if (t == 0) g_rowptr[0] = 0;
}

__global__ void k_fill(const int* __restrict__ ei) {
    int e = blockIdx.x * blockDim.x + threadIdx.x;
    if (e < E_) {
        int d = ei[E_ + e];
        int p = atomicAdd(&g_fill[d], 1);
        g_col[g_rowptr[d] + p] = ei[e];
    }
}

// ---------------- fused GeneralConv ------------------------------------------
// One block per node. Edge-outer gather: each thread keeps 16 accumulators
// (one per graph in its b-group) -> 16 independent L2 loads in flight per step.
__global__ void __launch_bounds__(256) k_conv(const float* __restrict__ x,
                                              const float* __restrict__ Wm,
                                              const float* __restrict__ bm) {
    __shared__ float Wsh[F_ * F_];
    __shared__ float accsh[64][68];    // [b][f], row = 272B (16B aligned)
    __shared__ int   adjsh[256];
    int n = blockIdx.x;
    int t = threadIdx.x;
    int f = t & 63, bl = t >> 6;

    for (int i = t; i < 1024; i += 256)
        ((float4*)Wsh)[i] = ((const float4*)Wm)[i];

    int r0 = g_rowptr[n], r1 = g_rowptr[n + 1];
    int deg = r1 - r0;
    float inv  = 1.f / fmaxf((float)deg, 1.f);
    float bias = (deg > 0) ? bm[f] : 0.f;

    float acc[16];
    #pragma unroll
    for (int i = 0; i < 16; i++) acc[i] = 0.f;

    const float* xb = x + (size_t)bl * 16 * IND + f;
    for (int base = r0; base < r1; base += 256) {
        int cnt = min(256, r1 - base);
        __syncthreads();
        if (t < cnt) adjsh[t] = g_col[base + t];
        __syncthreads();
        for (int j = 0; j < cnt; ++j) {
            const float* xp = xb + adjsh[j] * F_;
            #pragma unroll
            for (int i = 0; i < 16; i++) acc[i] += __ldg(xp + i * IND);
        }
    }
    __syncthreads();   // also covers Wsh when deg == 0

    #pragma unroll
    for (int i = 0; i < 16; i++) accsh[bl * 16 + i][f] = acc[i];
    __syncthreads();

    float wreg[64];    // this thread's W column
    #pragma unroll
    for (int k = 0; k < 64; k++) wreg[k] = Wsh[k * 64 + f];

    for (int i = 0; i < 16; i++) {
        int b = bl * 16 + i;
        const float4* arow = (const float4*)&accsh[b][0];
        float v = 0.f;
        #pragma unroll
        for (int k4 = 0; k4 < 16; k4++) {
            float4 a4 = arow[k4];
            v += a4.x * wreg[k4 * 4 + 0] + a4.y * wreg[k4 * 4 + 1]
               + a4.z * wreg[k4 * 4 + 2] + a4.w * wreg[k4 * 4 + 3];
        }
        v = v * inv + bias;
        float h = v + x[(b * N_ + n) * F_ + f];
        h = (h >= 0.f) ? h : 0.01f * h;
        g_xs[b * IND + n * F_ + f] = h;
    }
}

// ---------------- encoder GEMM: [64,64000]@[64000,512], tf32, split-K --------
// Block tile 64x256, warp tile 32x64 (2 m-warps x 4 n-warps).
// tf32 conversion at STS time; register-prefetch pipeline; no atomics.
__global__ void __launch_bounds__(256) k_gemm_enc(const float* __restrict__ W) {
    __shared__ unsigned Ash[64][36];     // pad 4: conflict-free frag reads
    __shared__ unsigned Bsh[32][264];    // pad 8: conflict-free frag reads
    const int nblk = blockIdx.x;         // 0..1
    const int kblk = blockIdx.y;         // 0..99
    const int t = threadIdx.x;
    const int lane = t & 31, warp = t >> 5;
    const int gid = lane >> 2, tid4 = lane & 3;
    const int m0 = (warp & 1) * 32, nb = (warp >> 1) * 64;
    const int la_m = t >> 2, la_k = (t & 3) * 8;
    const int lb_k = t >> 3, lb_c = (t & 7) * 4;
    const int kbase0 = kblk * (ENC_TILES * 32);
    const int ncol0 = nblk * 256;

    float acc[2][8][4];
    #pragma unroll
    for (int a = 0; a < 2; a++)
        #pragma unroll
        for (int i = 0; i < 8; i++)
            #pragma unroll
            for (int j = 0; j < 4; j++) acc[a][i][j] = 0.f;

    float4 ra0, ra1, rb[8];
    {
        const float4* ap = (const float4*)&g_xs[la_m * IND + kbase0 + la_k];
        ra0 = ap[0]; ra1 = ap[1];
        const float* brow = &W[(kbase0 + lb_k) * HID + ncol0 + lb_c];
        #pragma unroll
        for (int q = 0; q < 8; q++) rb[q] = *(const float4*)&brow[q * 32];
    }
    for (int it = 0; it < ENC_TILES; ++it) {
        __syncthreads();
        Ash[la_m][la_k + 0] = f2tf32(ra0.x); Ash[la_m][la_k + 1] = f2tf32(ra0.y);
        Ash[la_m][la_k + 2] = f2tf32(ra0.z); Ash[la_m][la_k + 3] = f2tf32(ra0.w);
        Ash[la_m][la_k + 4] = f2tf32(ra1.x); Ash[la_m][la_k + 5] = f2tf32(ra1.y);
        Ash[la_m][la_k + 6] = f2tf32(ra1.z); Ash[la_m][la_k + 7] = f2tf32(ra1.w);
        #pragma unroll
        for (int q = 0; q < 8; q++) {
            Bsh[lb_k][lb_c + q * 32 + 0] = f2tf32(rb[q].x);
            Bsh[lb_k][lb_c + q * 32 + 1] = f2tf32(rb[q].y);
            Bsh[lb_k][lb_c + q * 32 + 2] = f2tf32(rb[q].z);
            Bsh[lb_k][lb_c + q * 32 + 3] = f2tf32(rb[q].w);
        }
        __syncthreads();
        if (it + 1 < ENC_TILES) {
            int kb = kbase0 + (it + 1) * 32;
            const float4* ap = (const float4*)&g_xs[la_m * IND + kb + la_k];
            ra0 = ap[0]; ra1 = ap[1];
            const float* brow = &W[(kb + lb_k) * HID + ncol0 + lb_c];
            #pragma unroll
            for (int q = 0; q < 8; q++) rb[q] = *(const float4*)&brow[q * 32];
        }
        #pragma unroll
        for (int kk = 0; kk < 32; kk += 8) {
            unsigned a0[2], a1[2], a2[2], a3[2];
            #pragma unroll
            for (int mi = 0; mi < 2; mi++) {
                int mr = m0 + mi * 16 + gid;
                a0[mi] = Ash[mr][kk + tid4];     a1[mi] = Ash[mr + 8][kk + tid4];
                a2[mi] = Ash[mr][kk + tid4 + 4]; a3[mi] = Ash[mr + 8][kk + tid4 + 4];
            }
            #pragma unroll
            for (int nt = 0; nt < 8; nt++) {
                int nn = nb + nt * 8 + gid;
                unsigned b0 = Bsh[kk + tid4][nn];
                unsigned b1 = Bsh[kk + tid4 + 4][nn];
                mma_tf32(acc[0][nt], a0[0], a1[0], a2[0], a3[0], b0, b1);
                mma_tf32(acc[1][nt], a0[1], a1[1], a2[1], a3[1], b0, b1);
            }
        }
    }
    float* P = g_part + kblk * (B_ * HID) + ncol0;
    #pragma unroll
    for (int mi = 0; mi < 2; mi++)
        #pragma unroll
        for (int nt = 0; nt < 8; nt++) {
            int m = m0 + mi * 16 + gid;
            int nn = nb + nt * 8 + tid4 * 2;
            *(float2*)&P[m * HID + nn]       = make_float2(acc[mi][nt][0], acc[mi][nt][1]);
            *(float2*)&P[(m + 8) * HID + nn] = make_float2(acc[mi][nt][2], acc[mi][nt][3]);
        }
}

// reduce split-K partials + bias + relu
__global__ void k_enc_epi(const float* __restrict__ be1) {
    int i = blockIdx.x * 512 + threadIdx.x;     // grid 64 x 512 = 32768
    float s = 0.f;
    #pragma unroll 5
    for (int kb = 0; kb < ENC_KBLK; kb++) s += g_part[kb * (B_ * HID) + i];
    g_he[i] = fmaxf(s + be1[i & (HID - 1)], 0.f);
}

// ---------------- mean/log_var/z + hd, merged --------------------------------
__global__ void __launch_bounds__(512) k_mid(const float* __restrict__ Wmean,
                                             const float* __restrict__ bmean,
                                             const float* __restrict__ Wlv,
                                             const float* __restrict__ blv,
                                             const float* __restrict__ eps,
                                             const float* __restrict__ Wd1,
                                             const float* __restrict__ bd1,
                                             float* __restrict__ out_mean,
                                             float* __restrict__ out_lv) {
    __shared__ float hesh[HID];
    __shared__ float zsh[L_];
    int b = blockIdx.x, t = threadIdx.x;
    hesh[t] = g_he[b * HID + t];
    __syncthreads();
    if (t < L_) {
        float m = 0.f, v = 0.f;
        #pragma unroll 8
        for (int k = 0; k < HID; ++k) {
            float h = hesh[k];
            m += h * Wmean[k * L_ + t];
            v += h * Wlv[k * L_ + t];
        }
        m += bmean[t]; v += blv[t];
        out_mean[b * L_ + t] = m;
        out_lv[b * L_ + t]   = v;
        zsh[t] = m + expf(0.5f * v) * eps[b * L_ + t];
    }
    __syncthreads();
    float a = 0.f;
    #pragma unroll 8
    for (int k = 0; k < L_; ++k) a += zsh[k] * Wd1[k * HID + t];
    g_hd[b * HID + t] = fmaxf(a + bd1[t], 0.f);
}

// ---------------- decoder GEMM: [64,512]@[512,64000] + bias + sigmoid --------
__global__ void __launch_bounds__(256) k_gemm_dec(const float* __restrict__ W,
                                                  const float* __restrict__ bd2,
                                                  float* __restrict__ out) {
    __shared__ unsigned Ash[64][36];
    __shared__ unsigned Bsh[32][264];
    const int nblk = blockIdx.x;         // 0..249
    const int t = threadIdx.x;
    const int lane = t & 31, warp = t >> 5;
    const int gid = lane >> 2, tid4 = lane & 3;
    const int m0 = (warp & 1) * 32, nb = (warp >> 1) * 64;
    const int la_m = t >> 2, la_k = (t & 3) * 8;
    const int lb_k = t >> 3, lb_c = (t & 7) * 4;
    const int ncol0 = nblk * 256;

    float acc[2][8][4];
    #pragma unroll
    for (int a = 0; a < 2; a++)
        #pragma unroll
        for (int i = 0; i < 8; i++)
            #pragma unroll
            for (int j = 0; j < 4; j++) acc[a][i][j] = 0.f;

    float4 ra0, ra1, rb[8];
    {
        const float4* ap = (const float4*)&g_hd[la_m * HID + la_k];
        ra0 = ap[0]; ra1 = ap[1];
        const float* brow = &W[lb_k * IND + ncol0 + lb_c];
        #pragma unroll
        for (int q = 0; q < 8; q++) rb[q] = *(const float4*)&brow[q * 32];
    }
    for (int it = 0; it < DEC_TILES; ++it) {
        __syncthreads();
        Ash[la_m][la_k + 0] = f2tf32(ra0.x); Ash[la_m][la_k + 1] = f2tf32(ra0.y);
        Ash[la_m][la_k + 2] = f2tf32(ra0.z); Ash[la_m][la_k + 3] = f2tf32(ra0.w);
        Ash[la_m][la_k + 4] = f2tf32(ra1.x); Ash[la_m][la_k + 5] = f2tf32(ra1.y);
        Ash[la_m][la_k + 6] = f2tf32(ra1.z); Ash[la_m][la_k + 7] = f2tf32(ra1.w);
        #pragma unroll
        for (int q = 0; q < 8; q++) {
            Bsh[lb_k][lb_c + q * 32 + 0] = f2tf32(rb[q].x);
            Bsh[lb_k][lb_c + q * 32 + 1] = f2tf32(rb[q].y);
            Bsh[lb_k][lb_c + q * 32 + 2] = f2tf32(rb[q].z);
            Bsh[lb_k][lb_c + q * 32 + 3] = f2tf32(rb[q].w);
        }
        __syncthreads();
        if (it + 1 < DEC_TILES) {
            int kb = (it + 1) * 32;
            const float4* ap = (const float4*)&g_hd[la_m * HID + kb + la_k];
            ra0 = ap[0]; ra1 = ap[1];
            const float* brow = &W[(kb + lb_k) * IND + ncol0 + lb_c];
            #pragma unroll
            for (int q = 0; q < 8; q++) rb[q] = *(const float4*)&brow[q * 32];
        }
        #pragma unroll
        for (int kk = 0; kk < 32; kk += 8) {
            unsigned a0[2], a1[2], a2[2], a3[2];
            #pragma unroll
            for (int mi = 0; mi < 2; mi++) {
                int mr = m0 + mi * 16 + gid;
                a0[mi] = Ash[mr][kk + tid4];     a1[mi] = Ash[mr + 8][kk + tid4];
                a2[mi] = Ash[mr][kk + tid4 + 4]; a3[mi] = Ash[mr + 8][kk + tid4 + 4];
            }
            #pragma unroll
            for (int nt = 0; nt < 8; nt++) {
                int nn = nb + nt * 8 + gid;
                unsigned b0 = Bsh[kk + tid4][nn];
                unsigned b1 = Bsh[kk + tid4 + 4][nn];
                mma_tf32(acc[0][nt], a0[0], a1[0], a2[0], a3[0], b0, b1);
                mma_tf32(acc[1][nt], a0[1], a1[1], a2[1], a3[1], b0, b1);
            }
        }
    }
    const float* bb = &bd2[ncol0];
    #pragma unroll
    for (int mi = 0; mi < 2; mi++)
        #pragma unroll
        for (int nt = 0; nt < 8; nt++) {
            int m = m0 + mi * 16 + gid;
            int nn = nb + nt * 8 + tid4 * 2;
            float bv0 = bb[nn], bv1 = bb[nn + 1];
            float v0 = acc[mi][nt][0] + bv0, v1 = acc[mi][nt][1] + bv1;
            float v2 = acc[mi][nt][2] + bv0, v3 = acc[mi][nt][3] + bv1;
            float2 r0 = make_float2(1.f / (1.f + __expf(-v0)), 1.f / (1.f + __expf(-v1)));
            float2 r1 = make_float2(1.f / (1.f + __expf(-v2)), 1.f / (1.f + __expf(-v3)));
            *(float2*)&out[m * IND + ncol0 + nn]       = r0;
            *(float2*)&out[(m + 8) * IND + ncol0 + nn] = r1;
        }
}

// ---------------- launch -----------------------------------------------------
extern "C" void kernel_launch(void* const* d_in, const int* in_sizes, int n_in,
                              void* d_out, int out_size) {
    const float* x      = (const float*)d_in[0];
    const int*   ei     = (const int*)d_in[1];
    const float* eps    = (const float*)d_in[2];
    const float* Wmsg   = (const float*)d_in[3];
    const float* bmsg   = (const float*)d_in[4];
    const float* We1    = (const float*)d_in[5];
    const float* be1    = (const float*)d_in[6];
    const float* Wmean  = (const float*)d_in[7];
    const float* bmean  = (const float*)d_in[8];
    const float* Wlv    = (const float*)d_in[9];
    const float* blv    = (const float*)d_in[10];
    const float* Wd1    = (const float*)d_in[11];
    const float* bd1    = (const float*)d_in[12];
    const float* Wd2    = (const float*)d_in[13];
    const float* bd2    = (const float*)d_in[14];

    float* out      = (float*)d_out;
    float* out_xhat = out;
    float* out_mean = out + (size_t)B_ * IND;
    float* out_lv   = out_mean + B_ * L_;

    k_init<<<1, 1024>>>();
    k_count<<<32, 1024>>>(ei);
    k_scan<<<1, 1024>>>();
    k_fill<<<125, 256>>>(ei);
    k_conv<<<N_, 256>>>(x, Wmsg, bmsg);
    k_gemm_enc<<<dim3(2, ENC_KBLK), 256>>>(We1);
    k_enc_epi<<<64, 512>>>(be1);
    k_mid<<<B_, 512>>>(Wmean, bmean, Wlv, blv, eps, Wd1, bd1, out_mean, out_lv);
    k_gemm_dec<<<250, 256>>>(Wd2, bd2, out_xhat);
}

// round 4
// speedup vs baseline: 1.6623x; 1.1011x over previous
#include <cuda_runtime.h>

#define B_   64
#define N_   1000
#define F_   64
#define E_   32000
#define IND  64000
#define HID  512
#define L_   128
#define ENC_KBLK 100
#define ENC_TILES 20
#define DEC_TILES 16

// ---------------- scratch ----------------------------------------------------
__device__ int   g_rowptr[N_ + 1];
__device__ int   g_col[E_];
__device__ float g_xs[B_ * IND];
__device__ float g_part[ENC_KBLK * B_ * HID];
__device__ float g_he[B_ * HID];
__device__ float g_hd[B_ * HID];

// ---------------- helpers ----------------------------------------------------
__device__ __forceinline__ unsigned f2tf32(float f) {
    unsigned r;
    asm("cvt.rna.tf32.f32 %0, %1;" : "=r"(r) : "f"(f));
    return r;
}

__device__ __forceinline__ void mma_tf32(float c[4],
                                         unsigned a0, unsigned a1, unsigned a2, unsigned a3,
                                         unsigned b0, unsigned b1) {
    asm volatile(
        "mma.sync.aligned.m16n8k8.row.col.f32.tf32.tf32.f32 "
        "{%0,%1,%2,%3}, {%4,%5,%6,%7}, {%8,%9}, {%0,%1,%2,%3};"
        : "+f"(c[0]), "+f"(c[1]), "+f"(c[2]), "+f"(c[3])
        : "r"(a0), "r"(a1), "r"(a2), "r"(a3), "r"(b0), "r"(b1));
}

__device__ __forceinline__ void cp16(void* dst, const void* src) {
    unsigned d = (unsigned)__cvta_generic_to_shared(dst);
    asm volatile("cp.async.cg.shared.global [%0], [%1], 16;" :: "r"(d), "l"(src));
}
__device__ __forceinline__ void cp_commit() { asm volatile("cp.async.commit_group;"); }
__device__ __forceinline__ void cp_wait1()  { asm volatile("cp.async.wait_group 1;"); }
__device__ __forceinline__ void cp_wait0()  { asm volatile("cp.async.wait_group 0;"); }

// smem swizzles (replace padding; preserve 16B cp.async alignment)
#define ASW(m, c) ((c) ^ (((m) & 7) * 4))     // A: 64 x 32 fp32 rows
#define BSW(k, c) ((c) ^ (((k) & 3) * 8))     // B: 32 x 128 fp32 rows

// ---------------- CSR build: ONE single-block kernel -------------------------
__global__ void __launch_bounds__(1024) k_csr(const int* __restrict__ ei) {
    __shared__ int hist[1024];   // degree (preserved)
    __shared__ int rp[1024];     // inclusive scan
    __shared__ int fil[N_];
    int t = threadIdx.x;
    hist[t] = 0;
    if (t < N_) fil[t] = 0;
    __syncthreads();
    #pragma unroll 4
    for (int e = t; e < E_; e += 1024) atomicAdd(&hist[ei[E_ + e]], 1);
    __syncthreads();
    rp[t] = hist[t];
    __syncthreads();
    for (int off = 1; off < 1024; off <<= 1) {
        int v = (t >= off) ? rp[t - off] : 0;
        __syncthreads();
        rp[t] += v;
        __syncthreads();
    }
    if (t < N_) g_rowptr[t + 1] = rp[t];
    if (t == 0) g_rowptr[0] = 0;
    __syncthreads();
    #pragma unroll 4
    for (int e = t; e < E_; e += 1024) {
        int d = ei[E_ + e];
        int p = atomicAdd(&fil[d], 1);
        g_col[(rp[d] - hist[d]) + p] = ei[e];
    }
}

__global__ void k_nop() {}

// ---------------- fused GeneralConv ------------------------------------------
__global__ void __launch_bounds__(256) k_conv(const float* __restrict__ x,
                                              const float* __restrict__ Wm,
                                              const float* __restrict__ bm) {
    __shared__ float Wsh[F_ * F_];
    __shared__ float accsh[64][68];
    __shared__ int   adjsh[256];
    int n = blockIdx.x;
    int t = threadIdx.x;
    int f = t & 63, bl = t >> 6;

    for (int i = t; i < 1024; i += 256)
        ((float4*)Wsh)[i] = ((const float4*)Wm)[i];

    int r0 = g_rowptr[n], r1 = g_rowptr[n + 1];
    int deg = r1 - r0;
    float inv  = 1.f / fmaxf((float)deg, 1.f);
    float bias = (deg > 0) ? bm[f] : 0.f;

    float acc[16];
    #pragma unroll
    for (int i = 0; i < 16; i++) acc[i] = 0.f;

    const float* xb = x + (size_t)bl * 16 * IND + f;
    for (int base = r0; base < r1; base += 256) {
        int cnt = min(256, r1 - base);
        __syncthreads();
        if (t < cnt) adjsh[t] = g_col[base + t];
        __syncthreads();
        for (int j = 0; j < cnt; ++j) {
            const float* xp = xb + adjsh[j] * F_;
            #pragma unroll
            for (int i = 0; i < 16; i++) acc[i] += __ldg(xp + i * IND);
        }
    }
    __syncthreads();

    #pragma unroll
    for (int i = 0; i < 16; i++) accsh[bl * 16 + i][f] = acc[i];
    __syncthreads();

    float wreg[64];
    #pragma unroll
    for (int k = 0; k < 64; k++) wreg[k] = Wsh[k * 64 + f];

    for (int i = 0; i < 16; i++) {
        int b = bl * 16 + i;
        const float4* arow = (const float4*)&accsh[b][0];
        float v = 0.f;
        #pragma unroll
        for (int k4 = 0; k4 < 16; k4++) {
            float4 a4 = arow[k4];
            v += a4.x * wreg[k4 * 4 + 0] + a4.y * wreg[k4 * 4 + 1]
               + a4.z * wreg[k4 * 4 + 2] + a4.w * wreg[k4 * 4 + 3];
        }
        v = v * inv + bias;
        float h = v + x[(b * N_ + n) * F_ + f];
        h = (h >= 0.f) ? h : 0.01f * h;
        g_xs[b * IND + n * F_ + f] = h;
    }
}

// ---------------- encoder GEMM: [64,64000]@[64000,512], split-K --------------
// Block tile 64x128, 8 warps (2m x 4n), warp tile 32x32.
// 2-stage cp.async pipeline, static smem = 48KB exactly, XOR-swizzled.
__global__ void __launch_bounds__(256) k_gemm_enc(const float* __restrict__ W) {
    __shared__ float As[2][64][32];      // 16384 B
    __shared__ float Bs[2][32][128];     // 32768 B
    const int nblk = blockIdx.x;          // 0..3
    const int kblk = blockIdx.y;          // 0..99
    const int t = threadIdx.x;
    const int lane = t & 31, warp = t >> 5;
    const int gid = lane >> 2, tid4 = lane & 3;
    const int m0w = (warp & 1) * 32, nbw = (warp >> 1) * 32;
    const int la_m = t >> 2, la_k = (t & 3) * 8;
    const int lb_k = t >> 3, lb_c = (t & 7) * 16;
    const int kbase0 = kblk * 640;
    const int ncol0 = nblk * 128;

    float acc[2][4][4];
    #pragma unroll
    for (int a = 0; a < 2; a++)
        #pragma unroll
        for (int i = 0; i < 4; i++)
            #pragma unroll
            for (int j = 0; j < 4; j++) acc[a][i][j] = 0.f;

    auto issue = [&](int it, int buf) {
        const float* ag = &g_xs[la_m * IND + kbase0 + it * 32 + la_k];
        cp16(&As[buf][la_m][ASW(la_m, la_k)], ag);
        cp16(&As[buf][la_m][ASW(la_m, la_k + 4)], ag + 4);
        const float* bg = &W[(kbase0 + it * 32 + lb_k) * HID + ncol0 + lb_c];
        #pragma unroll
        for (int q = 0; q < 4; q++)
            cp16(&Bs[buf][lb_k][BSW(lb_k, lb_c + q * 4)], bg + q * 4);
    };

    issue(0, 0); cp_commit();
    issue(1, 1); cp_commit();

    for (int it = 0; it < ENC_TILES; ++it) {
        if (it + 1 < ENC_TILES) cp_wait1(); else cp_wait0();
        __syncthreads();
        const int s = it & 1;
        #pragma unroll
        for (int kk = 0; kk < 32; kk += 8) {
            unsigned a0[2], a1[2], a2[2], a3[2];
            #pragma unroll
            for (int mi = 0; mi < 2; mi++) {
                int mr = m0w + mi * 16 + gid;
                a0[mi] = f2tf32(As[s][mr][ASW(mr, kk + tid4)]);
                a1[mi] = f2tf32(As[s][mr + 8][ASW(mr + 8, kk + tid4)]);
                a2[mi] = f2tf32(As[s][mr][ASW(mr, kk + tid4 + 4)]);
                a3[mi] = f2tf32(As[s][mr + 8][ASW(mr + 8, kk + tid4 + 4)]);
            }
            #pragma unroll
            for (int nt = 0; nt < 4; nt++) {
                int nn = nbw + nt * 8 + gid;
                unsigned b0 = f2tf32(Bs[s][kk + tid4][BSW(kk + tid4, nn)]);
                unsigned b1 = f2tf32(Bs[s][kk + tid4 + 4][BSW(kk + tid4 + 4, nn)]);
                mma_tf32(acc[0][nt], a0[0], a1[0], a2[0], a3[0], b0, b1);
                mma_tf32(acc[1][nt], a0[1], a1[1], a2[1], a3[1], b0, b1);
            }
        }
        __syncthreads();
        if (it + 2 < ENC_TILES) { issue(it + 2, s); cp_commit(); }
    }
    float* P = g_part + kblk * (B_ * HID) + ncol0;
    #pragma unroll
    for (int mi = 0; mi < 2; mi++)
        #pragma unroll
        for (int nt = 0; nt < 4; nt++) {
            int m = m0w + mi * 16 + gid;
            int nn = nbw + nt * 8 + tid4 * 2;
            *(float2*)&P[m * HID + nn]       = make_float2(acc[mi][nt][0], acc[mi][nt][1]);
            *(float2*)&P[(m + 8) * HID + nn] = make_float2(acc[mi][nt][2], acc[mi][nt][3]);
        }
}

// reduce split-K partials + bias + relu
__global__ void k_enc_epi(const float* __restrict__ be1) {
    int i = blockIdx.x * 512 + threadIdx.x;
    float s = 0.f;
    #pragma unroll 5
    for (int kb = 0; kb < ENC_KBLK; kb++) s += g_part[kb * (B_ * HID) + i];
    g_he[i] = fmaxf(s + be1[i & (HID - 1)], 0.f);
}

// ---------------- mean/log_var/z + hd, merged --------------------------------
__global__ void __launch_bounds__(512) k_mid(const float* __restrict__ Wmean,
                                             const float* __restrict__ bmean,
                                             const float* __restrict__ Wlv,
                                             const float* __restrict__ blv,
                                             const float* __restrict__ eps,
                                             const float* __restrict__ Wd1,
                                             const float* __restrict__ bd1,
                                             float* __restrict__ out_mean,
                                             float* __restrict__ out_lv) {
    __shared__ float hesh[HID];
    __shared__ float mpart[4][L_], vpart[4][L_];
    __shared__ float zsh[L_];
    int b = blockIdx.x, t = threadIdx.x;
    hesh[t] = g_he[b * HID + t];
    __syncthreads();
    int l = t & 127, kq = t >> 7;
    float m = 0.f, v = 0.f;
    #pragma unroll 8
    for (int k = kq * 128; k < (kq + 1) * 128; ++k) {
        float h = hesh[k];
        m += h * Wmean[k * L_ + l];
        v += h * Wlv[k * L_ + l];
    }
    mpart[kq][l] = m; vpart[kq][l] = v;
    __syncthreads();
    if (t < L_) {
        m = mpart[0][t] + mpart[1][t] + mpart[2][t] + mpart[3][t] + bmean[t];
        v = vpart[0][t] + vpart[1][t] + vpart[2][t] + vpart[3][t] + blv[t];
        out_mean[b * L_ + t] = m;
        out_lv[b * L_ + t]   = v;
        zsh[t] = m + expf(0.5f * v) * eps[b * L_ + t];
    }
    __syncthreads();
    float a = 0.f;
    #pragma unroll 8
    for (int k = 0; k < L_; ++k) a += zsh[k] * Wd1[k * HID + t];
    g_hd[b * HID + t] = fmaxf(a + bd1[t], 0.f);
}

// ---------------- decoder GEMM: [64,512]@[512,64000] + bias + sigmoid --------
__global__ void __launch_bounds__(256) k_gemm_dec(const float* __restrict__ W,
                                                  const float* __restrict__ bd2,
                                                  float* __restrict__ out) {
    __shared__ float As[2][64][32];
    __shared__ float Bs[2][32][128];
    const int nblk = blockIdx.x;          // 0..499
    const int t = threadIdx.x;
    const int lane = t & 31, warp = t >> 5;
    const int gid = lane >> 2, tid4 = lane & 3;
    const int m0w = (warp & 1) * 32, nbw = (warp >> 1) * 32;
    const int la_m = t >> 2, la_k = (t & 3) * 8;
    const int lb_k = t >> 3, lb_c = (t & 7) * 16;
    const int ncol0 = nblk * 128;

    float acc[2][4][4];
    #pragma unroll
    for (int a = 0; a < 2; a++)
        #pragma unroll
        for (int i = 0; i < 4; i++)
            #pragma unroll
            for (int j = 0; j < 4; j++) acc[a][i][j] = 0.f;

    auto issue = [&](int it, int buf) {
        const float* ag = &g_hd[la_m * HID + it * 32 + la_k];
        cp16(&As[buf][la_m][ASW(la_m, la_k)], ag);
        cp16(&As[buf][la_m][ASW(la_m, la_k + 4)], ag + 4);
        const float* bg = &W[(it * 32 + lb_k) * IND + ncol0 + lb_c];
        #pragma unroll
        for (int q = 0; q < 4; q++)
            cp16(&Bs[buf][lb_k][BSW(lb_k, lb_c + q * 4)], bg + q * 4);
    };

    issue(0, 0); cp_commit();
    issue(1, 1); cp_commit();

    for (int it = 0; it < DEC_TILES; ++it) {
        if (it + 1 < DEC_TILES) cp_wait1(); else cp_wait0();
        __syncthreads();
        const int s = it & 1;
        #pragma unroll
        for (int kk = 0; kk < 32; kk += 8) {
            unsigned a0[2], a1[2], a2[2], a3[2];
            #pragma unroll
            for (int mi = 0; mi < 2; mi++) {
                int mr = m0w + mi * 16 + gid;
                a0[mi] = f2tf32(As[s][mr][ASW(mr, kk + tid4)]);
                a1[mi] = f2tf32(As[s][mr + 8][ASW(mr + 8, kk + tid4)]);
                a2[mi] = f2tf32(As[s][mr][ASW(mr, kk + tid4 + 4)]);
                a3[mi] = f2tf32(As[s][mr + 8][ASW(mr + 8, kk + tid4 + 4)]);
            }
            #pragma unroll
            for (int nt = 0; nt < 4; nt++) {
                int nn = nbw + nt * 8 + gid;
                unsigned b0 = f2tf32(Bs[s][kk + tid4][BSW(kk + tid4, nn)]);
                unsigned b1 = f2tf32(Bs[s][kk + tid4 + 4][BSW(kk + tid4 + 4, nn)]);
                mma_tf32(acc[0][nt], a0[0], a1[0], a2[0], a3[0], b0, b1);
                mma_tf32(acc[1][nt], a0[1], a1[1], a2[1], a3[1], b0, b1);
            }
        }
        __syncthreads();
        if (it + 2 < DEC_TILES) { issue(it + 2, s); cp_commit(); }
    }
    const float* bb = &bd2[ncol0];
    #pragma unroll
    for (int mi = 0; mi < 2; mi++)
        #pragma unroll
        for (int nt = 0; nt < 4; nt++) {
            int m = m0w + mi * 16 + gid;
            int nn = nbw + nt * 8 + tid4 * 2;
            float bv0 = bb[nn], bv1 = bb[nn + 1];
            float v0 = acc[mi][nt][0] + bv0, v1 = acc[mi][nt][1] + bv1;
            float v2 = acc[mi][nt][2] + bv0, v3 = acc[mi][nt][3] + bv1;
            float2 r0 = make_float2(1.f / (1.f + __expf(-v0)), 1.f / (1.f + __expf(-v1)));
            float2 r1 = make_float2(1.f / (1.f + __expf(-v2)), 1.f / (1.f + __expf(-v3)));
            *(float2*)&out[m * IND + ncol0 + nn]       = r0;
            *(float2*)&out[(m + 8) * IND + ncol0 + nn] = r1;
        }
}

// ---------------- launch -----------------------------------------------------
extern "C" void kernel_launch(void* const* d_in, const int* in_sizes, int n_in,
                              void* d_out, int out_size) {
    const float* x      = (const float*)d_in[0];
    const int*   ei     = (const int*)d_in[1];
    const float* eps    = (const float*)d_in[2];
    const float* Wmsg   = (const float*)d_in[3];
    const float* bmsg   = (const float*)d_in[4];
    const float* We1    = (const float*)d_in[5];
    const float* be1    = (const float*)d_in[6];
    const float* Wmean  = (const float*)d_in[7];
    const float* bmean  = (const float*)d_in[8];
    const float* Wlv    = (const float*)d_in[9];
    const float* blv    = (const float*)d_in[10];
    const float* Wd1    = (const float*)d_in[11];
    const float* bd1    = (const float*)d_in[12];
    const float* Wd2    = (const float*)d_in[13];
    const float* bd2    = (const float*)d_in[14];

    float* out      = (float*)d_out;
    float* out_xhat = out;
    float* out_mean = out + (size_t)B_ * IND;
    float* out_lv   = out_mean + B_ * L_;

    k_csr<<<1, 1024>>>(ei);                                  // 0
    k_nop<<<1, 32>>>();                                      // 1
    k_nop<<<1, 32>>>();                                      // 2
    k_conv<<<N_, 256>>>(x, Wmsg, bmsg);                      // 3  <- ncu capture slot
    k_gemm_enc<<<dim3(4, ENC_KBLK), 256>>>(We1);             // 4
    k_enc_epi<<<64, 512>>>(be1);                             // 5
    k_mid<<<B_, 512>>>(Wmean, bmean, Wlv, blv, eps, Wd1, bd1, out_mean, out_lv); // 6
    k_gemm_dec<<<500, 256>>>(Wd2, bd2, out_xhat);            // 7
}

// round 5
// speedup vs baseline: 1.8577x; 1.1175x over previous
#include <cuda_runtime.h>

#define B_   64
#define N_   1000
#define F_   64
#define E_   32000
#define IND  64000
#define HID  512
#define L_   128
#define ENC_KBLK 100
#define ENC_TILES 20
#define DEC_TILES 16

// ---------------- scratch ----------------------------------------------------
__device__ int   g_deg[N_];          // zero-init; re-zeroed by k_scan each pass
__device__ int   g_fill[N_];         // zero-init; re-zeroed by k_scan each pass
__device__ int   g_rowptr[N_ + 1];
__device__ int   g_col[E_];
__device__ float g_xs[B_ * IND];
__device__ float g_part[ENC_KBLK * B_ * HID];
__device__ float g_he[B_ * HID];
__device__ float g_hd[B_ * HID];

// ---------------- helpers ----------------------------------------------------
__device__ __forceinline__ unsigned f2tf32(float f) {
    unsigned r;
    asm("cvt.rna.tf32.f32 %0, %1;" : "=r"(r) : "f"(f));
    return r;
}
__device__ __forceinline__ float tf32r(float f) {   // value rounded to tf32 grid
    return __uint_as_float(f2tf32(f));
}

__device__ __forceinline__ void mma_tf32(float c[4],
                                         unsigned a0, unsigned a1, unsigned a2, unsigned a3,
                                         unsigned b0, unsigned b1) {
    asm volatile(
        "mma.sync.aligned.m16n8k8.row.col.f32.tf32.tf32.f32 "
        "{%0,%1,%2,%3}, {%4,%5,%6,%7}, {%8,%9}, {%0,%1,%2,%3};"
        : "+f"(c[0]), "+f"(c[1]), "+f"(c[2]), "+f"(c[3])
        : "r"(a0), "r"(a1), "r"(a2), "r"(a3), "r"(b0), "r"(b1));
}

__device__ __forceinline__ void cp16(void* dst, const void* src) {
    unsigned d = (unsigned)__cvta_generic_to_shared(dst);
    asm volatile("cp.async.cg.shared.global [%0], [%1], 16;" :: "r"(d), "l"(src));
}
__device__ __forceinline__ void cp_commit() { asm volatile("cp.async.commit_group;"); }
__device__ __forceinline__ void cp_wait1()  { asm volatile("cp.async.wait_group 1;"); }
__device__ __forceinline__ void cp_wait0()  { asm volatile("cp.async.wait_group 0;"); }

// smem swizzles (bank-conflict-free, preserve 16B cp.async alignment)
#define ASW(m, c) ((c) ^ (((m) & 7) * 4))
#define BSW(k, c) ((c) ^ (((k) & 3) * 8))

// ---------------- CSR build: parallel across SMs ------------------------------
__global__ void k_count(const int* __restrict__ ei) {
    int e = blockIdx.x * 256 + threadIdx.x;
    if (e < E_) atomicAdd(&g_deg[ei[E_ + e]], 1);
}

// scan + reset counters for next replay (globals are zero on first call)
__global__ void __launch_bounds__(1024) k_scan() {
    __shared__ int sh[1024];
    int t = threadIdx.x;
    sh[t] = (t < N_) ? g_deg[t] : 0;
    __syncthreads();
    for (int off = 1; off < 1024; off <<= 1) {
        int v = (t >= off) ? sh[t - off] : 0;
        __syncthreads();
        sh[t] += v;
        __syncthreads();
    }
    if (t < N_) g_rowptr[t + 1] = sh[t];
    if (t == 0) g_rowptr[0] = 0;
    if (t < N_) { g_deg[t] = 0; g_fill[t] = 0; }
}

__global__ void k_fill(const int* __restrict__ ei) {
    int e = blockIdx.x * 256 + threadIdx.x;
    if (e < E_) {
        int d = ei[E_ + e];
        int p = atomicAdd(&g_fill[d], 1);
        g_col[g_rowptr[d] + p] = ei[e];
    }
}

// ---------------- fused GeneralConv (float4, high occupancy) -----------------
// thread: q = t&15 (feature quad), g = t>>4 (4 graphs each)
__global__ void __launch_bounds__(256, 4) k_conv(const float* __restrict__ x,
                                                 const float* __restrict__ Wm,
                                                 const float* __restrict__ bm) {
    __shared__ float Wsh[F_ * F_];
    __shared__ float accsh[64][68];
    __shared__ int   adjsh[256];
    const int n = blockIdx.x;
    const int t = threadIdx.x;
    const int q = t & 15, g = t >> 4;

    for (int i = t; i < 1024; i += 256)
        ((float4*)Wsh)[i] = ((const float4*)Wm)[i];

    const int r0 = g_rowptr[n], r1 = g_rowptr[n + 1];
    const int deg = r1 - r0;
    const float inv = 1.f / fmaxf((float)deg, 1.f);

    float4 a0 = {0,0,0,0}, a1 = {0,0,0,0}, a2 = {0,0,0,0}, a3 = {0,0,0,0};

    // x viewed as float4: element (b, node s, quad q) at b*16000 + s*16 + q
    const float4* xq = (const float4*)x + (size_t)(g * 4) * 16000 + q;
    for (int base = r0; base < r1; base += 256) {
        int cnt = min(256, r1 - base);
        __syncthreads();
        if (t < cnt) adjsh[t] = g_col[base + t];
        __syncthreads();
        for (int j = 0; j < cnt; ++j) {
            const float4* p = xq + adjsh[j] * 16;
            float4 v0 = __ldg(p);
            float4 v1 = __ldg(p + 16000);
            float4 v2 = __ldg(p + 32000);
            float4 v3 = __ldg(p + 48000);
            a0.x += v0.x; a0.y += v0.y; a0.z += v0.z; a0.w += v0.w;
            a1.x += v1.x; a1.y += v1.y; a1.z += v1.z; a1.w += v1.w;
            a2.x += v2.x; a2.y += v2.y; a2.z += v2.z; a2.w += v2.w;
            a3.x += v3.x; a3.y += v3.y; a3.z += v3.z; a3.w += v3.w;
        }
    }
    __syncthreads();
    *(float4*)&accsh[g * 4 + 0][q * 4] = a0;
    *(float4*)&accsh[g * 4 + 1][q * 4] = a1;
    *(float4*)&accsh[g * 4 + 2][q * 4] = a2;
    *(float4*)&accsh[g * 4 + 3][q * 4] = a3;
    __syncthreads();

    float4 bias4 = {0,0,0,0};
    if (deg > 0) bias4 = ((const float4*)bm)[q];
    const float4* W4 = (const float4*)Wsh;     // W4[k*16 + q] = W[k][q*4..q*4+3]

    #pragma unroll
    for (int i = 0; i < 4; i++) {
        const int b = g * 4 + i;
        const float* arow = accsh[b];
        float4 v = {0,0,0,0};
        #pragma unroll 8
        for (int k = 0; k < 64; k++) {
            float a = arow[k];
            float4 w = W4[k * 16 + q];
            v.x += a * w.x; v.y += a * w.y; v.z += a * w.z; v.w += a * w.w;
        }
        float4 xr = __ldg((const float4*)(x + ((size_t)b * N_ + n) * 64) + q);
        float4 h;
        h.x = v.x * inv + bias4.x + xr.x;
        h.y = v.y * inv + bias4.y + xr.y;
        h.z = v.z * inv + bias4.z + xr.z;
        h.w = v.w * inv + bias4.w + xr.w;
        h.x = (h.x >= 0.f) ? h.x : 0.01f * h.x;
        h.y = (h.y >= 0.f) ? h.y : 0.01f * h.y;
        h.z = (h.z >= 0.f) ? h.z : 0.01f * h.z;
        h.w = (h.w >= 0.f) ? h.w : 0.01f * h.w;
        // pre-round to tf32 so the encoder GEMM can skip A-conversion
        h.x = tf32r(h.x); h.y = tf32r(h.y); h.z = tf32r(h.z); h.w = tf32r(h.w);
        *((float4*)(g_xs + (size_t)b * IND + n * 64) + q) = h;
    }
}

// ---------------- encoder GEMM: [64,64000]@[64000,512], split-K --------------
__global__ void __launch_bounds__(256) k_gemm_enc(const float* __restrict__ W) {
    __shared__ float As[2][64][32];
    __shared__ float Bs[2][32][128];
    const int nblk = blockIdx.x;          // 0..3
    const int kblk = blockIdx.y;          // 0..99
    const int t = threadIdx.x;
    const int lane = t & 31, warp = t >> 5;
    const int gid = lane >> 2, tid4 = lane & 3;
    const int m0w = (warp & 1) * 32, nbw = (warp >> 1) * 32;
    const int la_m = t >> 2, la_k = (t & 3) * 8;
    const int lb_k = t >> 3, lb_c = (t & 7) * 16;
    const int kbase0 = kblk * 640;
    const int ncol0 = nblk * 128;

    float acc[2][4][4];
    #pragma unroll
    for (int a = 0; a < 2; a++)
        #pragma unroll
        for (int i = 0; i < 4; i++)
            #pragma unroll
            for (int j = 0; j < 4; j++) acc[a][i][j] = 0.f;

    auto issue = [&](int it, int buf) {
        const float* ag = &g_xs[la_m * IND + kbase0 + it * 32 + la_k];
        cp16(&As[buf][la_m][ASW(la_m, la_k)], ag);
        cp16(&As[buf][la_m][ASW(la_m, la_k + 4)], ag + 4);
        const float* bg = &W[(kbase0 + it * 32 + lb_k) * HID + ncol0 + lb_c];
        #pragma unroll
        for (int q = 0; q < 4; q++)
            cp16(&Bs[buf][lb_k][BSW(lb_k, lb_c + q * 4)], bg + q * 4);
    };

    issue(0, 0); cp_commit();
    issue(1, 1); cp_commit();

    for (int it = 0; it < ENC_TILES; ++it) {
        if (it + 1 < ENC_TILES) cp_wait1(); else cp_wait0();
        __syncthreads();
        const int s = it & 1;
        #pragma unroll
        for (int kk = 0; kk < 32; kk += 8) {
            unsigned a0[2], a1[2], a2[2], a3[2];
            #pragma unroll
            for (int mi = 0; mi < 2; mi++) {
                int mr = m0w + mi * 16 + gid;
                a0[mi] = __float_as_uint(As[s][mr][ASW(mr, kk + tid4)]);
                a1[mi] = __float_as_uint(As[s][mr + 8][ASW(mr + 8, kk + tid4)]);
                a2[mi] = __float_as_uint(As[s][mr][ASW(mr, kk + tid4 + 4)]);
                a3[mi] = __float_as_uint(As[s][mr + 8][ASW(mr + 8, kk + tid4 + 4)]);
            }
            #pragma unroll
            for (int nt = 0; nt < 4; nt++) {
                int nn = nbw + nt * 8 + gid;
                unsigned b0 = f2tf32(Bs[s][kk + tid4][BSW(kk + tid4, nn)]);
                unsigned b1 = f2tf32(Bs[s][kk + tid4 + 4][BSW(kk + tid4 + 4, nn)]);
                mma_tf32(acc[0][nt], a0[0], a1[0], a2[0], a3[0], b0, b1);
                mma_tf32(acc[1][nt], a0[1], a1[1], a2[1], a3[1], b0, b1);
            }
        }
        __syncthreads();
        if (it + 2 < ENC_TILES) { issue(it + 2, s); cp_commit(); }
    }
    float* P = g_part + kblk * (B_ * HID) + ncol0;
    #pragma unroll
    for (int mi = 0; mi < 2; mi++)
        #pragma unroll
        for (int nt = 0; nt < 4; nt++) {
            int m = m0w + mi * 16 + gid;
            int nn = nbw + nt * 8 + tid4 * 2;
            *(float2*)&P[m * HID + nn]       = make_float2(acc[mi][nt][0], acc[mi][nt][1]);
            *(float2*)&P[(m + 8) * HID + nn] = make_float2(acc[mi][nt][2], acc[mi][nt][3]);
        }
}

// reduce split-K partials + bias + relu
__global__ void k_enc_epi(const float* __restrict__ be1) {
    int i = blockIdx.x * 512 + threadIdx.x;
    float s = 0.f;
    #pragma unroll 5
    for (int kb = 0; kb < ENC_KBLK; kb++) s += g_part[kb * (B_ * HID) + i];
    g_he[i] = fmaxf(s + be1[i & (HID - 1)], 0.f);
}

// ---------------- mean/log_var/z + hd, merged --------------------------------
__global__ void __launch_bounds__(512) k_mid(const float* __restrict__ Wmean,
                                             const float* __restrict__ bmean,
                                             const float* __restrict__ Wlv,
                                             const float* __restrict__ blv,
                                             const float* __restrict__ eps,
                                             const float* __restrict__ Wd1,
                                             const float* __restrict__ bd1,
                                             float* __restrict__ out_mean,
                                             float* __restrict__ out_lv) {
    __shared__ float hesh[HID];
    __shared__ float mpart[4][L_], vpart[4][L_];
    __shared__ float zsh[L_];
    int b = blockIdx.x, t = threadIdx.x;
    hesh[t] = g_he[b * HID + t];
    __syncthreads();
    int l = t & 127, kq = t >> 7;
    float m = 0.f, v = 0.f;
    #pragma unroll 8
    for (int k = kq * 128; k < (kq + 1) * 128; ++k) {
        float h = hesh[k];
        m += h * Wmean[k * L_ + l];
        v += h * Wlv[k * L_ + l];
    }
    mpart[kq][l] = m; vpart[kq][l] = v;
    __syncthreads();
    if (t < L_) {
        m = mpart[0][t] + mpart[1][t] + mpart[2][t] + mpart[3][t] + bmean[t];
        v = vpart[0][t] + vpart[1][t] + vpart[2][t] + vpart[3][t] + blv[t];
        out_mean[b * L_ + t] = m;
        out_lv[b * L_ + t]   = v;
        zsh[t] = m + expf(0.5f * v) * eps[b * L_ + t];
    }
    __syncthreads();
    float a = 0.f;
    #pragma unroll 8
    for (int k = 0; k < L_; ++k) a += zsh[k] * Wd1[k * HID + t];
    // pre-round to tf32 so the decoder GEMM can skip A-conversion
    g_hd[b * HID + t] = tf32r(fmaxf(a + bd1[t], 0.f));
}

// ---------------- decoder GEMM: [64,512]@[512,64000] + bias + sigmoid --------
__global__ void __launch_bounds__(256) k_gemm_dec(const float* __restrict__ W,
                                                  const float* __restrict__ bd2,
                                                  float* __restrict__ out) {
    __shared__ float As[2][64][32];
    __shared__ float Bs[2][32][128];
    const int nblk = blockIdx.x;          // 0..499
    const int t = threadIdx.x;
    const int lane = t & 31, warp = t >> 5;
    const int gid = lane >> 2, tid4 = lane & 3;
    const int m0w = (warp & 1) * 32, nbw = (warp >> 1) * 32;
    const int la_m = t >> 2, la_k = (t & 3) * 8;
    const int lb_k = t >> 3, lb_c = (t & 7) * 16;
    const int ncol0 = nblk * 128;

    float acc[2][4][4];
    #pragma unroll
    for (int a = 0; a < 2; a++)
        #pragma unroll
        for (int i = 0; i < 4; i++)
            #pragma unroll
            for (int j = 0; j < 4; j++) acc[a][i][j] = 0.f;

    auto issue = [&](int it, int buf) {
        const float* ag = &g_hd[la_m * HID + it * 32 + la_k];
        cp16(&As[buf][la_m][ASW(la_m, la_k)], ag);
        cp16(&As[buf][la_m][ASW(la_m, la_k + 4)], ag + 4);
        const float* bg = &W[(it * 32 + lb_k) * IND + ncol0 + lb_c];
        #pragma unroll
        for (int q = 0; q < 4; q++)
            cp16(&Bs[buf][lb_k][BSW(lb_k, lb_c + q * 4)], bg + q * 4);
    };

    issue(0, 0); cp_commit();
    issue(1, 1); cp_commit();

    for (int it = 0; it < DEC_TILES; ++it) {
        if (it + 1 < DEC_TILES) cp_wait1(); else cp_wait0();
        __syncthreads();
        const int s = it & 1;
        #pragma unroll
        for (int kk = 0; kk < 32; kk += 8) {
            unsigned a0[2], a1[2], a2[2], a3[2];
            #pragma unroll
            for (int mi = 0; mi < 2; mi++) {
                int mr = m0w + mi * 16 + gid;
                a0[mi] = __float_as_uint(As[s][mr][ASW(mr, kk + tid4)]);
                a1[mi] = __float_as_uint(As[s][mr + 8][ASW(mr + 8, kk + tid4)]);
                a2[mi] = __float_as_uint(As[s][mr][ASW(mr, kk + tid4 + 4)]);
                a3[mi] = __float_as_uint(As[s][mr + 8][ASW(mr + 8, kk + tid4 + 4)]);
            }
            #pragma unroll
            for (int nt = 0; nt < 4; nt++) {
                int nn = nbw + nt * 8 + gid;
                unsigned b0 = f2tf32(Bs[s][kk + tid4][BSW(kk + tid4, nn)]);
                unsigned b1 = f2tf32(Bs[s][kk + tid4 + 4][BSW(kk + tid4 + 4, nn)]);
                mma_tf32(acc[0][nt], a0[0], a1[0], a2[0], a3[0], b0, b1);
                mma_tf32(acc[1][nt], a0[1], a1[1], a2[1], a3[1], b0, b1);
            }
        }
        __syncthreads();
        if (it + 2 < DEC_TILES) { issue(it + 2, s); cp_commit(); }
    }
    const float* bb = &bd2[ncol0];
    #pragma unroll
    for (int mi = 0; mi < 2; mi++)
        #pragma unroll
        for (int nt = 0; nt < 4; nt++) {
            int m = m0w + mi * 16 + gid;
            int nn = nbw + nt * 8 + tid4 * 2;
            float bv0 = bb[nn], bv1 = bb[nn + 1];
            float v0 = acc[mi][nt][0] + bv0, v1 = acc[mi][nt][1] + bv1;
            float v2 = acc[mi][nt][2] + bv0, v3 = acc[mi][nt][3] + bv1;
            float2 r0 = make_float2(1.f / (1.f + __expf(-v0)), 1.f / (1.f + __expf(-v1)));
            float2 r1 = make_float2(1.f / (1.f + __expf(-v2)), 1.f / (1.f + __expf(-v3)));
            *(float2*)&out[m * IND + ncol0 + nn]       = r0;
            *(float2*)&out[(m + 8) * IND + ncol0 + nn] = r1;
        }
}

// ---------------- launch -----------------------------------------------------
extern "C" void kernel_launch(void* const* d_in, const int* in_sizes, int n_in,
                              void* d_out, int out_size) {
    const float* x      = (const float*)d_in[0];
    const int*   ei     = (const int*)d_in[1];
    const float* eps    = (const float*)d_in[2];
    const float* Wmsg   = (const float*)d_in[3];
    const float* bmsg   = (const float*)d_in[4];
    const float* We1    = (const float*)d_in[5];
    const float* be1    = (const float*)d_in[6];
    const float* Wmean  = (const float*)d_in[7];
    const float* bmean  = (const float*)d_in[8];
    const float* Wlv    = (const float*)d_in[9];
    const float* blv    = (const float*)d_in[10];
    const float* Wd1    = (const float*)d_in[11];
    const float* bd1    = (const float*)d_in[12];
    const float* Wd2    = (const float*)d_in[13];
    const float* bd2    = (const float*)d_in[14];

    float* out      = (float*)d_out;
    float* out_xhat = out;
    float* out_mean = out + (size_t)B_ * IND;
    float* out_lv   = out_mean + B_ * L_;

    k_count<<<125, 256>>>(ei);                               // 0
    k_scan<<<1, 1024>>>();                                   // 1
    k_fill<<<125, 256>>>(ei);                                // 2
    k_conv<<<N_, 256>>>(x, Wmsg, bmsg);                      // 3  <- ncu capture slot
    k_gemm_enc<<<dim3(4, ENC_KBLK), 256>>>(We1);             // 4
    k_enc_epi<<<64, 512>>>(be1);                             // 5
    k_mid<<<B_, 512>>>(Wmean, bmean, Wlv, blv, eps, Wd1, bd1, out_mean, out_lv); // 6
    k_gemm_dec<<<500, 256>>>(Wd2, bd2, out_xhat);            // 7
}

// round 7
// speedup vs baseline: 1.9327x; 1.0404x over previous
#include <cuda_runtime.h>
#include <cuda_bf16.h>

#define B_   64
#define N_   1000
#define F_   64
#define E_   32000
#define IND  64000
#define HID  512
#define L_   128
#define ENC_KBLK 100
#define ENC_TILES 20
#define DEC_TILES 16

// ---------------- scratch ----------------------------------------------------
__device__ int   g_deg[N_];          // zero-init; re-zeroed by k_scan each pass
__device__ int   g_fill[N_];
__device__ int   g_rowptr[N_ + 1];
__device__ int   g_col[E_];
__device__ uint4 g_xb4[B_ * IND / 8];   // x in bf16, 8 MB
__device__ float g_xs[B_ * IND];
__device__ float g_part[ENC_KBLK * B_ * HID];
__device__ float g_he[B_ * HID];
__device__ float g_hd[B_ * HID];

// ---------------- helpers ----------------------------------------------------
__device__ __forceinline__ unsigned f2tf32(float f) {
    unsigned r;
    asm("cvt.rna.tf32.f32 %0, %1;" : "=r"(r) : "f"(f));
    return r;
}
__device__ __forceinline__ float tf32r(float f) {
    return __uint_as_float(f2tf32(f));
}

__device__ __forceinline__ void mma_tf32(float c[4],
                                         unsigned a0, unsigned a1, unsigned a2, unsigned a3,
                                         unsigned b0, unsigned b1) {
    asm volatile(
        "mma.sync.aligned.m16n8k8.row.col.f32.tf32.tf32.f32 "
        "{%0,%1,%2,%3}, {%4,%5,%6,%7}, {%8,%9}, {%0,%1,%2,%3};"
        : "+f"(c[0]), "+f"(c[1]), "+f"(c[2]), "+f"(c[3])
        : "r"(a0), "r"(a1), "r"(a2), "r"(a3), "r"(b0), "r"(b1));
}

__device__ __forceinline__ void cp16(void* dst, const void* src) {
    unsigned d = (unsigned)__cvta_generic_to_shared(dst);
    asm volatile("cp.async.cg.shared.global [%0], [%1], 16;" :: "r"(d), "l"(src));
}
__device__ __forceinline__ void cp_commit() { asm volatile("cp.async.commit_group;"); }
__device__ __forceinline__ void cp_wait1()  { asm volatile("cp.async.wait_group 1;"); }
__device__ __forceinline__ void cp_wait0()  { asm volatile("cp.async.wait_group 0;"); }

#define ASW(m, c) ((c) ^ (((m) & 7) * 4))
#define BSW(k, c) ((c) ^ (((k) & 3) * 8))

__device__ __forceinline__ unsigned packbf(float lo, float hi) {
    __nv_bfloat162 h = __float22bfloat162_rn(make_float2(lo, hi));
    return *reinterpret_cast<unsigned*>(&h);
}
// accumulate 8 bf16 (one uint4) into 8 fp32
__device__ __forceinline__ void acc8(float* a, uint4 v) {
    unsigned u;
    u = v.x; a[0] += __uint_as_float(u << 16); a[1] += __uint_as_float(u & 0xffff0000u);
    u = v.y; a[2] += __uint_as_float(u << 16); a[3] += __uint_as_float(u & 0xffff0000u);
    u = v.z; a[4] += __uint_as_float(u << 16); a[5] += __uint_as_float(u & 0xffff0000u);
    u = v.w; a[6] += __uint_as_float(u << 16); a[7] += __uint_as_float(u & 0xffff0000u);
}

// ---------------- count + x->bf16 convert (fused) -----------------------------
// grid 2000 x 256 = 512000 threads = B*IND/8 EXACTLY (R6 had 2048 -> OOB!)
__global__ void __launch_bounds__(256) k_count_cvt(const int* __restrict__ ei,
                                                   const float* __restrict__ x) {
    int tid = blockIdx.x * 256 + threadIdx.x;
    const float4* xp = (const float4*)x + (size_t)tid * 2;
    float4 v0 = __ldg(xp), v1 = __ldg(xp + 1);
    g_xb4[tid] = make_uint4(packbf(v0.x, v0.y), packbf(v0.z, v0.w),
                            packbf(v1.x, v1.y), packbf(v1.z, v1.w));
    if (tid < E_) atomicAdd(&g_deg[ei[E_ + tid]], 1);
}

// scan + reset counters for next replay (globals are zero on first call)
__global__ void __launch_bounds__(1024) k_scan() {
    __shared__ int sh[1024];
    int t = threadIdx.x;
    sh[t] = (t < N_) ? g_deg[t] : 0;
    __syncthreads();
    for (int off = 1; off < 1024; off <<= 1) {
        int v = (t >= off) ? sh[t - off] : 0;
        __syncthreads();
        sh[t] += v;
        __syncthreads();
    }
    if (t < N_) g_rowptr[t + 1] = sh[t];
    if (t == 0) g_rowptr[0] = 0;
    if (t < N_) { g_deg[t] = 0; g_fill[t] = 0; }
}

__global__ void k_fill(const int* __restrict__ ei) {
    int e = blockIdx.x * 256 + threadIdx.x;
    if (e < E_) {
        int d = ei[E_ + e];
        int p = atomicAdd(&g_fill[d], 1);
        g_col[g_rowptr[d] + p] = ei[e];
    }
}

// ---------------- fused GeneralConv (bf16 gather, fp32 accumulate) -----------
// gather phase: oct = t&7 (8 feats), g = t>>3 (2 graphs each)
__global__ void __launch_bounds__(256, 4) k_conv(const float* __restrict__ x,
                                                 const float* __restrict__ Wm,
                                                 const float* __restrict__ bm) {
    __shared__ float Wsh[F_ * F_];
    __shared__ float accsh[64][68];
    __shared__ int   adjsh[256];
    const int n = blockIdx.x;
    const int t = threadIdx.x;
    const int oct = t & 7, g = t >> 3;

    for (int i = t; i < 1024; i += 256)
        ((float4*)Wsh)[i] = ((const float4*)Wm)[i];

    const int r0 = g_rowptr[n], r1 = g_rowptr[n + 1];
    const int deg = r1 - r0;
    const float inv = 1.f / fmaxf((float)deg, 1.f);

    float acc[2][8];
    #pragma unroll
    for (int i = 0; i < 2; i++)
        #pragma unroll
        for (int k = 0; k < 8; k++) acc[i][k] = 0.f;

    // uint4 index of (b, node s, oct): b*8000 + s*8 + oct
    const uint4* xq = g_xb4 + (size_t)(g * 2) * 8000 + oct;
    for (int base = r0; base < r1; base += 256) {
        int cnt = min(256, r1 - base);
        __syncthreads();
        if (t < cnt) adjsh[t] = g_col[base + t];
        __syncthreads();
        for (int j = 0; j < cnt; ++j) {
            const uint4* p = xq + adjsh[j] * 8;
            acc8(acc[0], __ldg(p));
            acc8(acc[1], __ldg(p + 8000));
        }
    }
    __syncthreads();
    #pragma unroll
    for (int i = 0; i < 2; i++)
        #pragma unroll
        for (int k = 0; k < 8; k++) accsh[g * 2 + i][oct * 8 + k] = acc[i][k];
    __syncthreads();

    // epilogue phase: q = t&15 (feature quad), gq = t>>4 (4 graphs each)
    const int q = t & 15, gq = t >> 4;
    float4 bias4 = {0,0,0,0};
    if (deg > 0) bias4 = ((const float4*)bm)[q];
    const float4* W4 = (const float4*)Wsh;

    #pragma unroll
    for (int i = 0; i < 4; i++) {
        const int b = gq * 4 + i;
        const float* arow = accsh[b];
        float4 v = {0,0,0,0};
        #pragma unroll 8
        for (int k = 0; k < 64; k++) {
            float a = arow[k];
            float4 w = W4[k * 16 + q];
            v.x += a * w.x; v.y += a * w.y; v.z += a * w.z; v.w += a * w.w;
        }
        float4 xr = __ldg((const float4*)(x + ((size_t)b * N_ + n) * 64) + q);
        float4 h;
        h.x = v.x * inv + bias4.x + xr.x;
        h.y = v.y * inv + bias4.y + xr.y;
        h.z = v.z * inv + bias4.z + xr.z;
        h.w = v.w * inv + bias4.w + xr.w;
        h.x = (h.x >= 0.f) ? h.x : 0.01f * h.x;
        h.y = (h.y >= 0.f) ? h.y : 0.01f * h.y;
        h.z = (h.z >= 0.f) ? h.z : 0.01f * h.z;
        h.w = (h.w >= 0.f) ? h.w : 0.01f * h.w;
        h.x = tf32r(h.x); h.y = tf32r(h.y); h.z = tf32r(h.z); h.w = tf32r(h.w);
        *((float4*)(g_xs + (size_t)b * IND + n * 64) + q) = h;
    }
}

// ---------------- encoder GEMM: [64,64000]@[64000,512], split-K --------------
__global__ void __launch_bounds__(256) k_gemm_enc(const float* __restrict__ W) {
    __shared__ float As[2][64][32];
    __shared__ float Bs[2][32][128];
    const int nblk = blockIdx.x;
    const int kblk = blockIdx.y;
    const int t = threadIdx.x;
    const int lane = t & 31, warp = t >> 5;
    const int gid = lane >> 2, tid4 = lane & 3;
    const int m0w = (warp & 1) * 32, nbw = (warp >> 1) * 32;
    const int la_m = t >> 2, la_k = (t & 3) * 8;
    const int lb_k = t >> 3, lb_c = (t & 7) * 16;
    const int kbase0 = kblk * 640;
    const int ncol0 = nblk * 128;

    float acc[2][4][4];
    #pragma unroll
    for (int a = 0; a < 2; a++)
        #pragma unroll
        for (int i = 0; i < 4; i++)
            #pragma unroll
            for (int j = 0; j < 4; j++) acc[a][i][j] = 0.f;

    auto issue = [&](int it, int buf) {
        const float* ag = &g_xs[la_m * IND + kbase0 + it * 32 + la_k];
        cp16(&As[buf][la_m][ASW(la_m, la_k)], ag);
        cp16(&As[buf][la_m][ASW(la_m, la_k + 4)], ag + 4);
        const float* bg = &W[(kbase0 + it * 32 + lb_k) * HID + ncol0 + lb_c];
        #pragma unroll
        for (int q = 0; q < 4; q++)
            cp16(&Bs[buf][lb_k][BSW(lb_k, lb_c + q * 4)], bg + q * 4);
    };

    issue(0, 0); cp_commit();
    issue(1, 1); cp_commit();

    for (int it = 0; it < ENC_TILES; ++it) {
        if (it + 1 < ENC_TILES) cp_wait1(); else cp_wait0();
        __syncthreads();
        const int s = it & 1;
        #pragma unroll
        for (int kk = 0; kk < 32; kk += 8) {
            unsigned a0[2], a1[2], a2[2], a3[2];
            #pragma unroll
            for (int mi = 0; mi < 2; mi++) {
                int mr = m0w + mi * 16 + gid;
                a0[mi] = __float_as_uint(As[s][mr][ASW(mr, kk + tid4)]);
                a1[mi] = __float_as_uint(As[s][mr + 8][ASW(mr + 8, kk + tid4)]);
                a2[mi] = __float_as_uint(As[s][mr][ASW(mr, kk + tid4 + 4)]);
                a3[mi] = __float_as_uint(As[s][mr + 8][ASW(mr + 8, kk + tid4 + 4)]);
            }
            #pragma unroll
            for (int nt = 0; nt < 4; nt++) {
                int nn = nbw + nt * 8 + gid;
                unsigned b0 = f2tf32(Bs[s][kk + tid4][BSW(kk + tid4, nn)]);
                unsigned b1 = f2tf32(Bs[s][kk + tid4 + 4][BSW(kk + tid4 + 4, nn)]);
                mma_tf32(acc[0][nt], a0[0], a1[0], a2[0], a3[0], b0, b1);
                mma_tf32(acc[1][nt], a0[1], a1[1], a2[1], a3[1], b0, b1);
            }
        }
        __syncthreads();
        if (it + 2 < ENC_TILES) { issue(it + 2, s); cp_commit(); }
    }
    float* P = g_part + kblk * (B_ * HID) + ncol0;
    #pragma unroll
    for (int mi = 0; mi < 2; mi++)
        #pragma unroll
        for (int nt = 0; nt < 4; nt++) {
            int m = m0w + mi * 16 + gid;
            int nn = nbw + nt * 8 + tid4 * 2;
            *(float2*)&P[m * HID + nn]       = make_float2(acc[mi][nt][0], acc[mi][nt][1]);
            *(float2*)&P[(m + 8) * HID + nn] = make_float2(acc[mi][nt][2], acc[mi][nt][3]);
        }
}

__global__ void k_enc_epi(const float* __restrict__ be1) {
    int i = blockIdx.x * 512 + threadIdx.x;
    float s = 0.f;
    #pragma unroll 5
    for (int kb = 0; kb < ENC_KBLK; kb++) s += g_part[kb * (B_ * HID) + i];
    g_he[i] = fmaxf(s + be1[i & (HID - 1)], 0.f);
}

// ---------------- mean/log_var/z + hd, merged --------------------------------
__global__ void __launch_bounds__(512) k_mid(const float* __restrict__ Wmean,
                                             const float* __restrict__ bmean,
                                             const float* __restrict__ Wlv,
                                             const float* __restrict__ blv,
                                             const float* __restrict__ eps,
                                             const float* __restrict__ Wd1,
                                             const float* __restrict__ bd1,
                                             float* __restrict__ out_mean,
                                             float* __restrict__ out_lv) {
    __shared__ float hesh[HID];
    __shared__ float mpart[4][L_], vpart[4][L_];
    __shared__ float zsh[L_];
    int b = blockIdx.x, t = threadIdx.x;
    hesh[t] = g_he[b * HID + t];
    __syncthreads();
    int l = t & 127, kq = t >> 7;
    float m = 0.f, v = 0.f;
    #pragma unroll 8
    for (int k = kq * 128; k < (kq + 1) * 128; ++k) {
        float h = hesh[k];
        m += h * Wmean[k * L_ + l];
        v += h * Wlv[k * L_ + l];
    }
    mpart[kq][l] = m; vpart[kq][l] = v;
    __syncthreads();
    if (t < L_) {
        m = mpart[0][t] + mpart[1][t] + mpart[2][t] + mpart[3][t] + bmean[t];
        v = vpart[0][t] + vpart[1][t] + vpart[2][t] + vpart[3][t] + blv[t];
        out_mean[b * L_ + t] = m;
        out_lv[b * L_ + t]   = v;
        zsh[t] = m + expf(0.5f * v) * eps[b * L_ + t];
    }
    __syncthreads();
    float a = 0.f;
    #pragma unroll 8
    for (int k = 0; k < L_; ++k) a += zsh[k] * Wd1[k * HID + t];
    g_hd[b * HID + t] = tf32r(fmaxf(a + bd1[t], 0.f));
}

// ---------------- decoder GEMM: [64,512]@[512,64000] + bias + sigmoid --------
__global__ void __launch_bounds__(256) k_gemm_dec(const float* __restrict__ W,
                                                  const float* __restrict__ bd2,
                                                  float* __restrict__ out) {
    __shared__ float As[2][64][32];
    __shared__ float Bs[2][32][128];
    const int nblk = blockIdx.x;
    const int t = threadIdx.x;
    const int lane = t & 31, warp = t >> 5;
    const int gid = lane >> 2, tid4 = lane & 3;
    const int m0w = (warp & 1) * 32, nbw = (warp >> 1) * 32;
    const int la_m = t >> 2, la_k = (t & 3) * 8;
    const int lb_k = t >> 3, lb_c = (t & 7) * 16;
    const int ncol0 = nblk * 128;

    float acc[2][4][4];
    #pragma unroll
    for (int a = 0; a < 2; a++)
        #pragma unroll
        for (int i = 0; i < 4; i++)
            #pragma unroll
            for (int j = 0; j < 4; j++) acc[a][i][j] = 0.f;

    auto issue = [&](int it, int buf) {
        const float* ag = &g_hd[la_m * HID + it * 32 + la_k];
        cp16(&As[buf][la_m][ASW(la_m, la_k)], ag);
        cp16(&As[buf][la_m][ASW(la_m, la_k + 4)], ag + 4);
        const float* bg = &W[(it * 32 + lb_k) * IND + ncol0 + lb_c];
        #pragma unroll
        for (int q = 0; q < 4; q++)
            cp16(&Bs[buf][lb_k][BSW(lb_k, lb_c + q * 4)], bg + q * 4);
    };

    issue(0, 0); cp_commit();
    issue(1, 1); cp_commit();

    for (int it = 0; it < DEC_TILES; ++it) {
        if (it + 1 < DEC_TILES) cp_wait1(); else cp_wait0();
        __syncthreads();
        const int s = it & 1;
        #pragma unroll
        for (int kk = 0; kk < 32; kk += 8) {
            unsigned a0[2], a1[2], a2[2], a3[2];
            #pragma unroll
            for (int mi = 0; mi < 2; mi++) {
                int mr = m0w + mi * 16 + gid;
                a0[mi] = __float_as_uint(As[s][mr][ASW(mr, kk + tid4)]);
                a1[mi] = __float_as_uint(As[s][mr + 8][ASW(mr + 8, kk + tid4)]);
                a2[mi] = __float_as_uint(As[s][mr][ASW(mr, kk + tid4 + 4)]);
                a3[mi] = __float_as_uint(As[s][mr + 8][ASW(mr + 8, kk + tid4 + 4)]);
            }
            #pragma unroll
            for (int nt = 0; nt < 4; nt++) {
                int nn = nbw + nt * 8 + gid;
                unsigned b0 = f2tf32(Bs[s][kk + tid4][BSW(kk + tid4, nn)]);
                unsigned b1 = f2tf32(Bs[s][kk + tid4 + 4][BSW(kk + tid4 + 4, nn)]);
                mma_tf32(acc[0][nt], a0[0], a1[0], a2[0], a3[0], b0, b1);
                mma_tf32(acc[1][nt], a0[1], a1[1], a2[1], a3[1], b0, b1);
            }
        }
        __syncthreads();
        if (it + 2 < DEC_TILES) { issue(it + 2, s); cp_commit(); }
    }
    const float* bb = &bd2[ncol0];
    #pragma unroll
    for (int mi = 0; mi < 2; mi++)
        #pragma unroll
        for (int nt = 0; nt < 4; nt++) {
            int m = m0w + mi * 16 + gid;
            int nn = nbw + nt * 8 + tid4 * 2;
            float bv0 = bb[nn], bv1 = bb[nn + 1];
            float v0 = acc[mi][nt][0] + bv0, v1 = acc[mi][nt][1] + bv1;
            float v2 = acc[mi][nt][2] + bv0, v3 = acc[mi][nt][3] + bv1;
            float2 r0 = make_float2(1.f / (1.f + __expf(-v0)), 1.f / (1.f + __expf(-v1)));
            float2 r1 = make_float2(1.f / (1.f + __expf(-v2)), 1.f / (1.f + __expf(-v3)));
            *(float2*)&out[m * IND + ncol0 + nn]       = r0;
            *(float2*)&out[(m + 8) * IND + ncol0 + nn] = r1;
        }
}

// ---------------- launch -----------------------------------------------------
extern "C" void kernel_launch(void* const* d_in, const int* in_sizes, int n_in,
                              void* d_out, int out_size) {
    const float* x      = (const float*)d_in[0];
    const int*   ei     = (const int*)d_in[1];
    const float* eps    = (const float*)d_in[2];
    const float* Wmsg   = (const float*)d_in[3];
    const float* bmsg   = (const float*)d_in[4];
    const float* We1    = (const float*)d_in[5];
    const float* be1    = (const float*)d_in[6];
    const float* Wmean  = (const float*)d_in[7];
    const float* bmean  = (const float*)d_in[8];
    const float* Wlv    = (const float*)d_in[9];
    const float* blv    = (const float*)d_in[10];
    const float* Wd1    = (const float*)d_in[11];
    const float* bd1    = (const float*)d_in[12];
    const float* Wd2    = (const float*)d_in[13];
    const float* bd2    = (const float*)d_in[14];

    float* out      = (float*)d_out;
    float* out_xhat = out;
    float* out_mean = out + (size_t)B_ * IND;
    float* out_lv   = out_mean + B_ * L_;

    k_count_cvt<<<2000, 256>>>(ei, x);                       // 0  (512000 threads exactly)
    k_scan<<<1, 1024>>>();                                   // 1
    k_fill<<<125, 256>>>(ei);                                // 2
    k_conv<<<N_, 256>>>(x, Wmsg, bmsg);                      // 3  <- ncu capture slot
    k_gemm_enc<<<dim3(4, ENC_KBLK), 256>>>(We1);             // 4
    k_enc_epi<<<64, 512>>>(be1);                             // 5
    k_mid<<<B_, 512>>>(Wmean, bmean, Wlv, blv, eps, Wd1, bd1, out_mean, out_lv); // 6
    k_gemm_dec<<<500, 256>>>(Wd2, bd2, out_xhat);            // 7
}

// round 8
// speedup vs baseline: 2.1318x; 1.1030x over previous
#include <cuda_runtime.h>
#include <cuda_bf16.h>

#define B_   64
#define N_   1000
#define F_   64
#define E_   32000
#define IND  64000
#define HID  512
#define L_   128
#define ENC_KBLK 100
#define ENC_TILES 20
#define DEC_TILES 16

// ---------------- scratch ----------------------------------------------------
__device__ int   g_deg[N_];          // zero-init; re-zeroed by k_scan each pass
__device__ int   g_fill[N_];
__device__ int   g_rowptr[N_ + 1];
__device__ int   g_col[E_];
__device__ uint4 g_xb4[B_ * IND / 8];   // x in bf16, 8 MB
__device__ float g_xs[B_ * IND];
__device__ float g_part[ENC_KBLK * B_ * HID];
__device__ float g_he[B_ * HID];
__device__ float g_hd[B_ * HID];

// ---------------- helpers ----------------------------------------------------
__device__ __forceinline__ unsigned f2tf32(float f) {
    unsigned r;
    asm("cvt.rna.tf32.f32 %0, %1;" : "=r"(r) : "f"(f));
    return r;
}
__device__ __forceinline__ float tf32r(float f) {
    return __uint_as_float(f2tf32(f));
}

__device__ __forceinline__ void mma_tf32(float c[4],
                                         unsigned a0, unsigned a1, unsigned a2, unsigned a3,
                                         unsigned b0, unsigned b1) {
    asm volatile(
        "mma.sync.aligned.m16n8k8.row.col.f32.tf32.tf32.f32 "
        "{%0,%1,%2,%3}, {%4,%5,%6,%7}, {%8,%9}, {%0,%1,%2,%3};"
        : "+f"(c[0]), "+f"(c[1]), "+f"(c[2]), "+f"(c[3])
        : "r"(a0), "r"(a1), "r"(a2), "r"(a3), "r"(b0), "r"(b1));
}

__device__ __forceinline__ void cp16(void* dst, const void* src) {
    unsigned d = (unsigned)__cvta_generic_to_shared(dst);
    asm volatile("cp.async.cg.shared.global [%0], [%1], 16;" :: "r"(d), "l"(src));
}
__device__ __forceinline__ void cp_commit() { asm volatile("cp.async.commit_group;"); }
__device__ __forceinline__ void cp_wait1()  { asm volatile("cp.async.wait_group 1;"); }
__device__ __forceinline__ void cp_wait0()  { asm volatile("cp.async.wait_group 0;"); }

#define ASW(m, c) ((c) ^ (((m) & 7) * 4))
#define BSW(k, c) ((c) ^ (((k) & 3) * 8))

__device__ __forceinline__ unsigned packbf(float lo, float hi) {
    __nv_bfloat162 h = __float22bfloat162_rn(make_float2(lo, hi));
    return *reinterpret_cast<unsigned*>(&h);
}
// accumulate 8 bf16 (one uint4) into 8 fp32
__device__ __forceinline__ void acc8(float* a, uint4 v) {
    unsigned u;
    u = v.x; a[0] += __uint_as_float(u << 16); a[1] += __uint_as_float(u & 0xffff0000u);
    u = v.y; a[2] += __uint_as_float(u << 16); a[3] += __uint_as_float(u & 0xffff0000u);
    u = v.z; a[4] += __uint_as_float(u << 16); a[5] += __uint_as_float(u & 0xffff0000u);
    u = v.w; a[6] += __uint_as_float(u << 16); a[7] += __uint_as_float(u & 0xffff0000u);
}

// ---------------- count + x->bf16 convert (fused) -----------------------------
// grid 2000 x 256 = 512000 threads = B*IND/8 EXACTLY
__global__ void __launch_bounds__(256) k_count_cvt(const int* __restrict__ ei,
                                                   const float* __restrict__ x) {
    int tid = blockIdx.x * 256 + threadIdx.x;
    const float4* xp = (const float4*)x + (size_t)tid * 2;
    float4 v0 = __ldg(xp), v1 = __ldg(xp + 1);
    g_xb4[tid] = make_uint4(packbf(v0.x, v0.y), packbf(v0.z, v0.w),
                            packbf(v1.x, v1.y), packbf(v1.z, v1.w));
    if (tid < E_) atomicAdd(&g_deg[ei[E_ + tid]], 1);
}

// scan + reset counters for next replay (globals are zero on first call)
__global__ void __launch_bounds__(1024) k_scan() {
    __shared__ int sh[1024];
    int t = threadIdx.x;
    sh[t] = (t < N_) ? g_deg[t] : 0;
    __syncthreads();
    for (int off = 1; off < 1024; off <<= 1) {
        int v = (t >= off) ? sh[t - off] : 0;
        __syncthreads();
        sh[t] += v;
        __syncthreads();
    }
    if (t < N_) g_rowptr[t + 1] = sh[t];
    if (t == 0) g_rowptr[0] = 0;
    if (t < N_) { g_deg[t] = 0; g_fill[t] = 0; }
}

__global__ void k_fill(const int* __restrict__ ei) {
    int e = blockIdx.x * 256 + threadIdx.x;
    if (e < E_) {
        int d = ei[E_ + e];
        int p = atomicAdd(&g_fill[d], 1);
        g_col[g_rowptr[d] + p] = ei[e];
    }
}

// ---------------- fused GeneralConv: bf16 gather + tf32-MMA epilogue ---------
// gather: oct = t&7 (8 feats), g = t>>3 (2 graphs each)
// epilogue: per-node [64 graphs x 64 feats] = accsh @ W via mma.m16n8k8
__global__ void __launch_bounds__(256, 4) k_conv(const float* __restrict__ x,
                                                 const float* __restrict__ Wm,
                                                 const float* __restrict__ bm) {
    __shared__ float Wsh[64][72];      // stride 72: B-frag banks tid4*8+gid distinct
    __shared__ float accsh[64][68];    // stride 68: A-frag banks gid*4+tid4 distinct
    __shared__ int   adjsh[256];
    const int n = blockIdx.x;
    const int t = threadIdx.x;
    const int oct = t & 7, g = t >> 3;

    for (int i = t; i < 4096; i += 256)
        Wsh[i >> 6][i & 63] = Wm[i];

    const int r0 = g_rowptr[n], r1 = g_rowptr[n + 1];
    const int deg = r1 - r0;
    const float inv = 1.f / fmaxf((float)deg, 1.f);

    float acc[2][8];
    #pragma unroll
    for (int i = 0; i < 2; i++)
        #pragma unroll
        for (int k = 0; k < 8; k++) acc[i][k] = 0.f;

    // uint4 index of (b, node s, oct): b*8000 + s*8 + oct
    const uint4* xq = g_xb4 + (size_t)(g * 2) * 8000 + oct;
    for (int base = r0; base < r1; base += 256) {
        int cnt = min(256, r1 - base);
        __syncthreads();
        if (t < cnt) adjsh[t] = g_col[base + t];
        __syncthreads();
        for (int j = 0; j < cnt; ++j) {
            const uint4* p = xq + adjsh[j] * 8;
            acc8(acc[0], __ldg(p));
            acc8(acc[1], __ldg(p + 8000));
        }
    }
    __syncthreads();
    #pragma unroll
    for (int i = 0; i < 2; i++)
        #pragma unroll
        for (int k = 0; k < 8; k++) accsh[g * 2 + i][oct * 8 + k] = acc[i][k];
    __syncthreads();

    // ---- MMA epilogue: D[64,64] = accsh @ Wsh ----
    const int warp = t >> 5, lane = t & 31;
    const int gid = lane >> 2, tid4 = lane & 3;
    const int m0 = (warp & 3) * 16;      // graph rows
    const int n0 = (warp >> 2) * 32;     // feat cols

    float c[4][4];
    #pragma unroll
    for (int i = 0; i < 4; i++)
        #pragma unroll
        for (int j = 0; j < 4; j++) c[i][j] = 0.f;

    #pragma unroll
    for (int kk = 0; kk < 64; kk += 8) {
        unsigned a0 = f2tf32(accsh[m0 + gid][kk + tid4]);
        unsigned a1 = f2tf32(accsh[m0 + gid + 8][kk + tid4]);
        unsigned a2 = f2tf32(accsh[m0 + gid][kk + tid4 + 4]);
        unsigned a3 = f2tf32(accsh[m0 + gid + 8][kk + tid4 + 4]);
        #pragma unroll
        for (int nt = 0; nt < 4; nt++) {
            int nn = n0 + nt * 8 + gid;
            unsigned b0 = f2tf32(Wsh[kk + tid4][nn]);
            unsigned b1 = f2tf32(Wsh[kk + tid4 + 4][nn]);
            mma_tf32(c[nt], a0, a1, a2, a3, b0, b1);
        }
    }

    #pragma unroll
    for (int nt = 0; nt < 4; nt++) {
        const int f0 = n0 + nt * 8 + tid4 * 2;
        float bv0 = 0.f, bv1 = 0.f;
        if (deg > 0) { bv0 = bm[f0]; bv1 = bm[f0 + 1]; }
        #pragma unroll
        for (int half = 0; half < 2; half++) {
            const int b = m0 + gid + half * 8;
            const float2 xr = *(const float2*)&x[((size_t)b * N_ + n) * 64 + f0];
            float h0 = c[nt][half * 2 + 0] * inv + bv0 + xr.x;
            float h1 = c[nt][half * 2 + 1] * inv + bv1 + xr.y;
            h0 = (h0 >= 0.f) ? h0 : 0.01f * h0;
            h1 = (h1 >= 0.f) ? h1 : 0.01f * h1;
            h0 = tf32r(h0); h1 = tf32r(h1);
            *(float2*)&g_xs[(size_t)b * IND + n * 64 + f0] = make_float2(h0, h1);
        }
    }
}

// ---------------- encoder GEMM: [64,64000]@[64000,512], split-K --------------
__global__ void __launch_bounds__(256) k_gemm_enc(const float* __restrict__ W) {
    __shared__ float As[2][64][32];
    __shared__ float Bs[2][32][128];
    const int nblk = blockIdx.x;
    const int kblk = blockIdx.y;
    const int t = threadIdx.x;
    const int lane = t & 31, warp = t >> 5;
    const int gid = lane >> 2, tid4 = lane & 3;
    const int m0w = (warp & 1) * 32, nbw = (warp >> 1) * 32;
    const int la_m = t >> 2, la_k = (t & 3) * 8;
    const int lb_k = t >> 3, lb_c = (t & 7) * 16;
    const int kbase0 = kblk * 640;
    const int ncol0 = nblk * 128;

    float acc[2][4][4];
    #pragma unroll
    for (int a = 0; a < 2; a++)
        #pragma unroll
        for (int i = 0; i < 4; i++)
            #pragma unroll
            for (int j = 0; j < 4; j++) acc[a][i][j] = 0.f;

    auto issue = [&](int it, int buf) {
        const float* ag = &g_xs[la_m * IND + kbase0 + it * 32 + la_k];
        cp16(&As[buf][la_m][ASW(la_m, la_k)], ag);
        cp16(&As[buf][la_m][ASW(la_m, la_k + 4)], ag + 4);
        const float* bg = &W[(kbase0 + it * 32 + lb_k) * HID + ncol0 + lb_c];
        #pragma unroll
        for (int q = 0; q < 4; q++)
            cp16(&Bs[buf][lb_k][BSW(lb_k, lb_c + q * 4)], bg + q * 4);
    };

    issue(0, 0); cp_commit();
    issue(1, 1); cp_commit();

    for (int it = 0; it < ENC_TILES; ++it) {
        if (it + 1 < ENC_TILES) cp_wait1(); else cp_wait0();
        __syncthreads();
        const int s = it & 1;
        #pragma unroll
        for (int kk = 0; kk < 32; kk += 8) {
            unsigned a0[2], a1[2], a2[2], a3[2];
            #pragma unroll
            for (int mi = 0; mi < 2; mi++) {
                int mr = m0w + mi * 16 + gid;
                a0[mi] = __float_as_uint(As[s][mr][ASW(mr, kk + tid4)]);
                a1[mi] = __float_as_uint(As[s][mr + 8][ASW(mr + 8, kk + tid4)]);
                a2[mi] = __float_as_uint(As[s][mr][ASW(mr, kk + tid4 + 4)]);
                a3[mi] = __float_as_uint(As[s][mr + 8][ASW(mr + 8, kk + tid4 + 4)]);
            }
            #pragma unroll
            for (int nt = 0; nt < 4; nt++) {
                int nn = nbw + nt * 8 + gid;
                unsigned b0 = f2tf32(Bs[s][kk + tid4][BSW(kk + tid4, nn)]);
                unsigned b1 = f2tf32(Bs[s][kk + tid4 + 4][BSW(kk + tid4 + 4, nn)]);
                mma_tf32(acc[0][nt], a0[0], a1[0], a2[0], a3[0], b0, b1);
                mma_tf32(acc[1][nt], a0[1], a1[1], a2[1], a3[1], b0, b1);
            }
        }
        __syncthreads();
        if (it + 2 < ENC_TILES) { issue(it + 2, s); cp_commit(); }
    }
    float* P = g_part + kblk * (B_ * HID) + ncol0;
    #pragma unroll
    for (int mi = 0; mi < 2; mi++)
        #pragma unroll
        for (int nt = 0; nt < 4; nt++) {
            int m = m0w + mi * 16 + gid;
            int nn = nbw + nt * 8 + tid4 * 2;
            *(float2*)&P[m * HID + nn]       = make_float2(acc[mi][nt][0], acc[mi][nt][1]);
            *(float2*)&P[(m + 8) * HID + nn] = make_float2(acc[mi][nt][2], acc[mi][nt][3]);
        }
}

__global__ void k_enc_epi(const float* __restrict__ be1) {
    int i = blockIdx.x * 512 + threadIdx.x;
    float s = 0.f;
    #pragma unroll 5
    for (int kb = 0; kb < ENC_KBLK; kb++) s += g_part[kb * (B_ * HID) + i];
    g_he[i] = fmaxf(s + be1[i & (HID - 1)], 0.f);
}

// ---------------- mean/log_var/z + hd, merged --------------------------------
__global__ void __launch_bounds__(512) k_mid(const float* __restrict__ Wmean,
                                             const float* __restrict__ bmean,
                                             const float* __restrict__ Wlv,
                                             const float* __restrict__ blv,
                                             const float* __restrict__ eps,
                                             const float* __restrict__ Wd1,
                                             const float* __restrict__ bd1,
                                             float* __restrict__ out_mean,
                                             float* __restrict__ out_lv) {
    __shared__ float hesh[HID];
    __shared__ float mpart[4][L_], vpart[4][L_];
    __shared__ float zsh[L_];
    int b = blockIdx.x, t = threadIdx.x;
    hesh[t] = g_he[b * HID + t];
    __syncthreads();
    int l = t & 127, kq = t >> 7;
    float m = 0.f, v = 0.f;
    #pragma unroll 8
    for (int k = kq * 128; k < (kq + 1) * 128; ++k) {
        float h = hesh[k];
        m += h * Wmean[k * L_ + l];
        v += h * Wlv[k * L_ + l];
    }
    mpart[kq][l] = m; vpart[kq][l] = v;
    __syncthreads();
    if (t < L_) {
        m = mpart[0][t] + mpart[1][t] + mpart[2][t] + mpart[3][t] + bmean[t];
        v = vpart[0][t] + vpart[1][t] + vpart[2][t] + vpart[3][t] + blv[t];
        out_mean[b * L_ + t] = m;
        out_lv[b * L_ + t]   = v;
        zsh[t] = m + expf(0.5f * v) * eps[b * L_ + t];
    }
    __syncthreads();
    float a = 0.f;
    #pragma unroll 8
    for (int k = 0; k < L_; ++k) a += zsh[k] * Wd1[k * HID + t];
    g_hd[b * HID + t] = tf32r(fmaxf(a + bd1[t], 0.f));
}

// ---------------- decoder GEMM: [64,512]@[512,64000] + bias + sigmoid --------
__global__ void __launch_bounds__(256) k_gemm_dec(const float* __restrict__ W,
                                                  const float* __restrict__ bd2,
                                                  float* __restrict__ out) {
    __shared__ float As[2][64][32];
    __shared__ float Bs[2][32][128];
    const int nblk = blockIdx.x;
    const int t = threadIdx.x;
    const int lane = t & 31, warp = t >> 5;
    const int gid = lane >> 2, tid4 = lane & 3;
    const int m0w = (warp & 1) * 32, nbw = (warp >> 1) * 32;
    const int la_m = t >> 2, la_k = (t & 3) * 8;
    const int lb_k = t >> 3, lb_c = (t & 7) * 16;
    const int ncol0 = nblk * 128;

    float acc[2][4][4];
    #pragma unroll
    for (int a = 0; a < 2; a++)
        #pragma unroll
        for (int i = 0; i < 4; i++)
            #pragma unroll
            for (int j = 0; j < 4; j++) acc[a][i][j] = 0.f;

    auto issue = [&](int it, int buf) {
        const float* ag = &g_hd[la_m * HID + it * 32 + la_k];
        cp16(&As[buf][la_m][ASW(la_m, la_k)], ag);
        cp16(&As[buf][la_m][ASW(la_m, la_k + 4)], ag + 4);
        const float* bg = &W[(it * 32 + lb_k) * IND + ncol0 + lb_c];
        #pragma unroll
        for (int q = 0; q < 4; q++)
            cp16(&Bs[buf][lb_k][BSW(lb_k, lb_c + q * 4)], bg + q * 4);
    };

    issue(0, 0); cp_commit();
    issue(1, 1); cp_commit();

    for (int it = 0; it < DEC_TILES; ++it) {
        if (it + 1 < DEC_TILES) cp_wait1(); else cp_wait0();
        __syncthreads();
        const int s = it & 1;
        #pragma unroll
        for (int kk = 0; kk < 32; kk += 8) {
            unsigned a0[2], a1[2], a2[2], a3[2];
            #pragma unroll
            for (int mi = 0; mi < 2; mi++) {
                int mr = m0w + mi * 16 + gid;
                a0[mi] = __float_as_uint(As[s][mr][ASW(mr, kk + tid4)]);
                a1[mi] = __float_as_uint(As[s][mr + 8][ASW(mr + 8, kk + tid4)]);
                a2[mi] = __float_as_uint(As[s][mr][ASW(mr, kk + tid4 + 4)]);
                a3[mi] = __float_as_uint(As[s][mr + 8][ASW(mr + 8, kk + tid4 + 4)]);
            }
            #pragma unroll
            for (int nt = 0; nt < 4; nt++) {
                int nn = nbw + nt * 8 + gid;
                unsigned b0 = f2tf32(Bs[s][kk + tid4][BSW(kk + tid4, nn)]);
                unsigned b1 = f2tf32(Bs[s][kk + tid4 + 4][BSW(kk + tid4 + 4, nn)]);
                mma_tf32(acc[0][nt], a0[0], a1[0], a2[0], a3[0], b0, b1);
                mma_tf32(acc[1][nt], a0[1], a1[1], a2[1], a3[1], b0, b1);
            }
        }
        __syncthreads();
        if (it + 2 < DEC_TILES) { issue(it + 2, s); cp_commit(); }
    }
    const float* bb = &bd2[ncol0];
    #pragma unroll
    for (int mi = 0; mi < 2; mi++)
        #pragma unroll
        for (int nt = 0; nt < 4; nt++) {
            int m = m0w + mi * 16 + gid;
            int nn = nbw + nt * 8 + tid4 * 2;
            float bv0 = bb[nn], bv1 = bb[nn + 1];
            float v0 = acc[mi][nt][0] + bv0, v1 = acc[mi][nt][1] + bv1;
            float v2 = acc[mi][nt][2] + bv0, v3 = acc[mi][nt][3] + bv1;
            float2 r0 = make_float2(1.f / (1.f + __expf(-v0)), 1.f / (1.f + __expf(-v1)));
            float2 r1 = make_float2(1.f / (1.f + __expf(-v2)), 1.f / (1.f + __expf(-v3)));
            *(float2*)&out[m * IND + ncol0 + nn]       = r0;
            *(float2*)&out[(m + 8) * IND + ncol0 + nn] = r1;
        }
}

// ---------------- launch -----------------------------------------------------
extern "C" void kernel_launch(void* const* d_in, const int* in_sizes, int n_in,
                              void* d_out, int out_size) {
    const float* x      = (const float*)d_in[0];
    const int*   ei     = (const int*)d_in[1];
    const float* eps    = (const float*)d_in[2];
    const float* Wmsg   = (const float*)d_in[3];
    const float* bmsg   = (const float*)d_in[4];
    const float* We1    = (const float*)d_in[5];
    const float* be1    = (const float*)d_in[6];
    const float* Wmean  = (const float*)d_in[7];
    const float* bmean  = (const float*)d_in[8];
    const float* Wlv    = (const float*)d_in[9];
    const float* blv    = (const float*)d_in[10];
    const float* Wd1    = (const float*)d_in[11];
    const float* bd1    = (const float*)d_in[12];
    const float* Wd2    = (const float*)d_in[13];
    const float* bd2    = (const float*)d_in[14];

    float* out      = (float*)d_out;
    float* out_xhat = out;
    float* out_mean = out + (size_t)B_ * IND;
    float* out_lv   = out_mean + B_ * L_;

    k_count_cvt<<<2000, 256>>>(ei, x);                       // 0
    k_scan<<<1, 1024>>>();                                   // 1
    k_fill<<<125, 256>>>(ei);                                // 2
    k_conv<<<N_, 256>>>(x, Wmsg, bmsg);                      // 3  <- ncu capture slot
    k_gemm_enc<<<dim3(4, ENC_KBLK), 256>>>(We1);             // 4
    k_enc_epi<<<64, 512>>>(be1);                             // 5
    k_mid<<<B_, 512>>>(Wmean, bmean, Wlv, blv, eps, Wd1, bd1, out_mean, out_lv); // 6
    k_gemm_dec<<<500, 256>>>(Wd2, bd2, out_xhat);            // 7
}

// round 9
// speedup vs baseline: 2.1399x; 1.0038x over previous
#include <cuda_runtime.h>
#include <cuda_bf16.h>

#define B_   64
#define N_   1000
#define F_   64
#define E_   32000
#define IND  64000
#define HID  512
#define L_   128
#define ENC_KBLK 100
#define ENC_TILES 20
#define DEC_TILES 16

// ---------------- scratch ----------------------------------------------------
__device__ int   g_deg[N_];          // zero-init; reset by k_conv after use
__device__ int   g_fill[N_];         // zero-init; reset by k_conv after use
__device__ int   g_rowptr[N_ + 1];
__device__ int   g_col[E_];
__device__ uint4 g_xb4[B_ * IND / 8];   // x in bf16, 8 MB
__device__ float g_xs[B_ * IND];
__device__ float g_part[ENC_KBLK * B_ * HID];
__device__ float g_hd[B_ * HID];

// ---------------- helpers ----------------------------------------------------
__device__ __forceinline__ unsigned f2tf32(float f) {
    unsigned r;
    asm("cvt.rna.tf32.f32 %0, %1;" : "=r"(r) : "f"(f));
    return r;
}
__device__ __forceinline__ float tf32r(float f) {
    return __uint_as_float(f2tf32(f));
}

__device__ __forceinline__ void mma_tf32(float c[4],
                                         unsigned a0, unsigned a1, unsigned a2, unsigned a3,
                                         unsigned b0, unsigned b1) {
    asm volatile(
        "mma.sync.aligned.m16n8k8.row.col.f32.tf32.tf32.f32 "
        "{%0,%1,%2,%3}, {%4,%5,%6,%7}, {%8,%9}, {%0,%1,%2,%3};"
        : "+f"(c[0]), "+f"(c[1]), "+f"(c[2]), "+f"(c[3])
        : "r"(a0), "r"(a1), "r"(a2), "r"(a3), "r"(b0), "r"(b1));
}

__device__ __forceinline__ void cp16(void* dst, const void* src) {
    unsigned d = (unsigned)__cvta_generic_to_shared(dst);
    asm volatile("cp.async.cg.shared.global [%0], [%1], 16;" :: "r"(d), "l"(src));
}
__device__ __forceinline__ void cp_commit() { asm volatile("cp.async.commit_group;"); }
__device__ __forceinline__ void cp_wait1()  { asm volatile("cp.async.wait_group 1;"); }
__device__ __forceinline__ void cp_wait0()  { asm volatile("cp.async.wait_group 0;"); }

#define ASW(m, c) ((c) ^ (((m) & 7) * 4))
#define BSW(k, c) ((c) ^ (((k) & 3) * 8))

__device__ __forceinline__ unsigned packbf(float lo, float hi) {
    __nv_bfloat162 h = __float22bfloat162_rn(make_float2(lo, hi));
    return *reinterpret_cast<unsigned*>(&h);
}
// accumulate 8 bf16 (one uint4) into 8 fp32
__device__ __forceinline__ void acc8(float* a, uint4 v) {
    unsigned u;
    u = v.x; a[0] += __uint_as_float(u << 16); a[1] += __uint_as_float(u & 0xffff0000u);
    u = v.y; a[2] += __uint_as_float(u << 16); a[3] += __uint_as_float(u & 0xffff0000u);
    u = v.z; a[4] += __uint_as_float(u << 16); a[5] += __uint_as_float(u & 0xffff0000u);
    u = v.w; a[6] += __uint_as_float(u << 16); a[7] += __uint_as_float(u & 0xffff0000u);
}

// ---------------- count + x->bf16 convert (fused) -----------------------------
// grid 2000 x 256 = 512000 threads = B*IND/8 EXACTLY
__global__ void __launch_bounds__(256) k_count_cvt(const int* __restrict__ ei,
                                                   const float* __restrict__ x) {
    int tid = blockIdx.x * 256 + threadIdx.x;
    const float4* xp = (const float4*)x + (size_t)tid * 2;
    float4 v0 = __ldg(xp), v1 = __ldg(xp + 1);
    g_xb4[tid] = make_uint4(packbf(v0.x, v0.y), packbf(v0.z, v0.w),
                            packbf(v1.x, v1.y), packbf(v1.z, v1.w));
    if (tid < E_) atomicAdd(&g_deg[ei[E_ + tid]], 1);
}

// ---------------- fill with per-block redundant scan --------------------------
// 32 blocks x 1024 threads; every block scans g_deg in smem (duplicated, cheap),
// block 0 also publishes g_rowptr for k_conv; then each block fills 1000 edges.
__global__ void __launch_bounds__(1024) k_fill_scan(const int* __restrict__ ei) {
    __shared__ int hist[1024];
    __shared__ int rp[1024];
    int t = threadIdx.x;
    int d0 = (t < N_) ? g_deg[t] : 0;
    hist[t] = d0;
    rp[t] = d0;
    __syncthreads();
    for (int off = 1; off < 1024; off <<= 1) {
        int v = (t >= off) ? rp[t - off] : 0;
        __syncthreads();
        rp[t] += v;
        __syncthreads();
    }
    if (blockIdx.x == 0) {
        if (t < N_) g_rowptr[t + 1] = rp[t];
        if (t == 0) g_rowptr[0] = 0;
    }
    if (t < 1000) {
        int e = blockIdx.x * 1000 + t;
        int d = ei[E_ + e];
        int p = atomicAdd(&g_fill[d], 1);
        g_col[(rp[d] - hist[d]) + p] = ei[e];
    }
}

// ---------------- fused GeneralConv: bf16 gather + tf32-MMA epilogue ---------
__global__ void __launch_bounds__(256, 4) k_conv(const float* __restrict__ x,
                                                 const float* __restrict__ Wm,
                                                 const float* __restrict__ bm) {
    __shared__ float Wsh[64][72];
    __shared__ float accsh[64][68];
    __shared__ int   adjsh[256];
    const int n = blockIdx.x;
    const int t = threadIdx.x;
    const int oct = t & 7, g = t >> 3;

    for (int i = t; i < 4096; i += 256)
        Wsh[i >> 6][i & 63] = Wm[i];

    const int r0 = g_rowptr[n], r1 = g_rowptr[n + 1];
    const int deg = r1 - r0;
    const float inv = 1.f / fmaxf((float)deg, 1.f);

    float acc[2][8];
    #pragma unroll
    for (int i = 0; i < 2; i++)
        #pragma unroll
        for (int k = 0; k < 8; k++) acc[i][k] = 0.f;

    const uint4* xq = g_xb4 + (size_t)(g * 2) * 8000 + oct;
    for (int base = r0; base < r1; base += 256) {
        int cnt = min(256, r1 - base);
        __syncthreads();
        if (t < cnt) adjsh[t] = g_col[base + t];
        __syncthreads();
        for (int j = 0; j < cnt; ++j) {
            const uint4* p = xq + adjsh[j] * 8;
            acc8(acc[0], __ldg(p));
            acc8(acc[1], __ldg(p + 8000));
        }
    }
    // CSR consumed for this node -> reset counters for the next graph replay
    if (t == 0) { g_deg[n] = 0; g_fill[n] = 0; }
    __syncthreads();
    #pragma unroll
    for (int i = 0; i < 2; i++)
        #pragma unroll
        for (int k = 0; k < 8; k++) accsh[g * 2 + i][oct * 8 + k] = acc[i][k];
    __syncthreads();

    // ---- MMA epilogue: D[64,64] = accsh @ Wsh ----
    const int warp = t >> 5, lane = t & 31;
    const int gid = lane >> 2, tid4 = lane & 3;
    const int m0 = (warp & 3) * 16;
    const int n0 = (warp >> 2) * 32;

    float c[4][4];
    #pragma unroll
    for (int i = 0; i < 4; i++)
        #pragma unroll
        for (int j = 0; j < 4; j++) c[i][j] = 0.f;

    #pragma unroll
    for (int kk = 0; kk < 64; kk += 8) {
        unsigned a0 = f2tf32(accsh[m0 + gid][kk + tid4]);
        unsigned a1 = f2tf32(accsh[m0 + gid + 8][kk + tid4]);
        unsigned a2 = f2tf32(accsh[m0 + gid][kk + tid4 + 4]);
        unsigned a3 = f2tf32(accsh[m0 + gid + 8][kk + tid4 + 4]);
        #pragma unroll
        for (int nt = 0; nt < 4; nt++) {
            int nn = n0 + nt * 8 + gid;
            unsigned b0 = f2tf32(Wsh[kk + tid4][nn]);
            unsigned b1 = f2tf32(Wsh[kk + tid4 + 4][nn]);
            mma_tf32(c[nt], a0, a1, a2, a3, b0, b1);
        }
    }

    #pragma unroll
    for (int nt = 0; nt < 4; nt++) {
        const int f0 = n0 + nt * 8 + tid4 * 2;
        float bv0 = 0.f, bv1 = 0.f;
        if (deg > 0) { bv0 = bm[f0]; bv1 = bm[f0 + 1]; }
        #pragma unroll
        for (int half = 0; half < 2; half++) {
            const int b = m0 + gid + half * 8;
            const float2 xr = *(const float2*)&x[((size_t)b * N_ + n) * 64 + f0];
            float h0 = c[nt][half * 2 + 0] * inv + bv0 + xr.x;
            float h1 = c[nt][half * 2 + 1] * inv + bv1 + xr.y;
            h0 = (h0 >= 0.f) ? h0 : 0.01f * h0;
            h1 = (h1 >= 0.f) ? h1 : 0.01f * h1;
            h0 = tf32r(h0); h1 = tf32r(h1);
            *(float2*)&g_xs[(size_t)b * IND + n * 64 + f0] = make_float2(h0, h1);
        }
    }
}

// ---------------- encoder GEMM: [64,64000]@[64000,512], split-K --------------
__global__ void __launch_bounds__(256) k_gemm_enc(const float* __restrict__ W) {
    __shared__ float As[2][64][32];
    __shared__ float Bs[2][32][128];
    const int nblk = blockIdx.x;
    const int kblk = blockIdx.y;
    const int t = threadIdx.x;
    const int lane = t & 31, warp = t >> 5;
    const int gid = lane >> 2, tid4 = lane & 3;
    const int m0w = (warp & 1) * 32, nbw = (warp >> 1) * 32;
    const int la_m = t >> 2, la_k = (t & 3) * 8;
    const int lb_k = t >> 3, lb_c = (t & 7) * 16;
    const int kbase0 = kblk * 640;
    const int ncol0 = nblk * 128;

    float acc[2][4][4];
    #pragma unroll
    for (int a = 0; a < 2; a++)
        #pragma unroll
        for (int i = 0; i < 4; i++)
            #pragma unroll
            for (int j = 0; j < 4; j++) acc[a][i][j] = 0.f;

    auto issue = [&](int it, int buf) {
        const float* ag = &g_xs[la_m * IND + kbase0 + it * 32 + la_k];
        cp16(&As[buf][la_m][ASW(la_m, la_k)], ag);
        cp16(&As[buf][la_m][ASW(la_m, la_k + 4)], ag + 4);
        const float* bg = &W[(kbase0 + it * 32 + lb_k) * HID + ncol0 + lb_c];
        #pragma unroll
        for (int q = 0; q < 4; q++)
            cp16(&Bs[buf][lb_k][BSW(lb_k, lb_c + q * 4)], bg + q * 4);
    };

    issue(0, 0); cp_commit();
    issue(1, 1); cp_commit();

    for (int it = 0; it < ENC_TILES; ++it) {
        if (it + 1 < ENC_TILES) cp_wait1(); else cp_wait0();
        __syncthreads();
        const int s = it & 1;
        #pragma unroll
        for (int kk = 0; kk < 32; kk += 8) {
            unsigned a0[2], a1[2], a2[2], a3[2];
            #pragma unroll
            for (int mi = 0; mi < 2; mi++) {
                int mr = m0w + mi * 16 + gid;
                a0[mi] = __float_as_uint(As[s][mr][ASW(mr, kk + tid4)]);
                a1[mi] = __float_as_uint(As[s][mr + 8][ASW(mr + 8, kk + tid4)]);
                a2[mi] = __float_as_uint(As[s][mr][ASW(mr, kk + tid4 + 4)]);
                a3[mi] = __float_as_uint(As[s][mr + 8][ASW(mr + 8, kk + tid4 + 4)]);
            }
            #pragma unroll
            for (int nt = 0; nt < 4; nt++) {
                int nn = nbw + nt * 8 + gid;
                unsigned b0 = f2tf32(Bs[s][kk + tid4][BSW(kk + tid4, nn)]);
                unsigned b1 = f2tf32(Bs[s][kk + tid4 + 4][BSW(kk + tid4 + 4, nn)]);
                mma_tf32(acc[0][nt], a0[0], a1[0], a2[0], a3[0], b0, b1);
                mma_tf32(acc[1][nt], a0[1], a1[1], a2[1], a3[1], b0, b1);
            }
        }
        __syncthreads();
        if (it + 2 < ENC_TILES) { issue(it + 2, s); cp_commit(); }
    }
    float* P = g_part + kblk * (B_ * HID) + ncol0;
    #pragma unroll
    for (int mi = 0; mi < 2; mi++)
        #pragma unroll
        for (int nt = 0; nt < 4; nt++) {
            int m = m0w + mi * 16 + gid;
            int nn = nbw + nt * 8 + tid4 * 2;
            *(float2*)&P[m * HID + nn]       = make_float2(acc[mi][nt][0], acc[mi][nt][1]);
            *(float2*)&P[(m + 8) * HID + nn] = make_float2(acc[mi][nt][2], acc[mi][nt][3]);
        }
}

// ---------------- fused: split-K reduce + bias/relu + mean/lv/z + hd ---------
__global__ void __launch_bounds__(512) k_mid(const float* __restrict__ be1,
                                             const float* __restrict__ Wmean,
                                             const float* __restrict__ bmean,
                                             const float* __restrict__ Wlv,
                                             const float* __restrict__ blv,
                                             const float* __restrict__ eps,
                                             const float* __restrict__ Wd1,
                                             const float* __restrict__ bd1,
                                             float* __restrict__ out_mean,
                                             float* __restrict__ out_lv) {
    __shared__ float hesh[HID];
    __shared__ float mpart[4][L_], vpart[4][L_];
    __shared__ float zsh[L_];
    int b = blockIdx.x, t = threadIdx.x;
    {   // he = relu(sum of 100 split-K partials + bias)
        float s = 0.f;
        const float* P = g_part + b * HID + t;
        #pragma unroll 5
        for (int kb = 0; kb < ENC_KBLK; kb++) s += P[kb * (B_ * HID)];
        hesh[t] = fmaxf(s + be1[t], 0.f);
    }
    __syncthreads();
    int l = t & 127, kq = t >> 7;
    float m = 0.f, v = 0.f;
    #pragma unroll 8
    for (int k = kq * 128; k < (kq + 1) * 128; ++k) {
        float h = hesh[k];
        m += h * Wmean[k * L_ + l];
        v += h * Wlv[k * L_ + l];
    }
    mpart[kq][l] = m; vpart[kq][l] = v;
    __syncthreads();
    if (t < L_) {
        m = mpart[0][t] + mpart[1][t] + mpart[2][t] + mpart[3][t] + bmean[t];
        v = vpart[0][t] + vpart[1][t] + vpart[2][t] + vpart[3][t] + blv[t];
        out_mean[b * L_ + t] = m;
        out_lv[b * L_ + t]   = v;
        zsh[t] = m + expf(0.5f * v) * eps[b * L_ + t];
    }
    __syncthreads();
    float a = 0.f;
    #pragma unroll 8
    for (int k = 0; k < L_; ++k) a += zsh[k] * Wd1[k * HID + t];
    g_hd[b * HID + t] = tf32r(fmaxf(a + bd1[t], 0.f));
}

// ---------------- decoder GEMM: [64,512]@[512,64000] + bias + sigmoid --------
__global__ void __launch_bounds__(256) k_gemm_dec(const float* __restrict__ W,
                                                  const float* __restrict__ bd2,
                                                  float* __restrict__ out) {
    __shared__ float As[2][64][32];
    __shared__ float Bs[2][32][128];
    const int nblk = blockIdx.x;
    const int t = threadIdx.x;
    const int lane = t & 31, warp = t >> 5;
    const int gid = lane >> 2, tid4 = lane & 3;
    const int m0w = (warp & 1) * 32, nbw = (warp >> 1) * 32;
    const int la_m = t >> 2, la_k = (t & 3) * 8;
    const int lb_k = t >> 3, lb_c = (t & 7) * 16;
    const int ncol0 = nblk * 128;

    float acc[2][4][4];
    #pragma unroll
    for (int a = 0; a < 2; a++)
        #pragma unroll
        for (int i = 0; i < 4; i++)
            #pragma unroll
            for (int j = 0; j < 4; j++) acc[a][i][j] = 0.f;

    auto issue = [&](int it, int buf) {
        const float* ag = &g_hd[la_m * HID + it * 32 + la_k];
        cp16(&As[buf][la_m][ASW(la_m, la_k)], ag);
        cp16(&As[buf][la_m][ASW(la_m, la_k + 4)], ag + 4);
        const float* bg = &W[(it * 32 + lb_k) * IND + ncol0 + lb_c];
        #pragma unroll
        for (int q = 0; q < 4; q++)
            cp16(&Bs[buf][lb_k][BSW(lb_k, lb_c + q * 4)], bg + q * 4);
    };

    issue(0, 0); cp_commit();
    issue(1, 1); cp_commit();

    for (int it = 0; it < DEC_TILES; ++it) {
        if (it + 1 < DEC_TILES) cp_wait1(); else cp_wait0();
        __syncthreads();
        const int s = it & 1;
        #pragma unroll
        for (int kk = 0; kk < 32; kk += 8) {
            unsigned a0[2], a1[2], a2[2], a3[2];
            #pragma unroll
            for (int mi = 0; mi < 2; mi++) {
                int mr = m0w + mi * 16 + gid;
                a0[mi] = __float_as_uint(As[s][mr][ASW(mr, kk + tid4)]);
                a1[mi] = __float_as_uint(As[s][mr + 8][ASW(mr + 8, kk + tid4)]);
                a2[mi] = __float_as_uint(As[s][mr][ASW(mr, kk + tid4 + 4)]);
                a3[mi] = __float_as_uint(As[s][mr + 8][ASW(mr + 8, kk + tid4 + 4)]);
            }
            #pragma unroll
            for (int nt = 0; nt < 4; nt++) {
                int nn = nbw + nt * 8 + gid;
                unsigned b0 = f2tf32(Bs[s][kk + tid4][BSW(kk + tid4, nn)]);
                unsigned b1 = f2tf32(Bs[s][kk + tid4 + 4][BSW(kk + tid4 + 4, nn)]);
                mma_tf32(acc[0][nt], a0[0], a1[0], a2[0], a3[0], b0, b1);
                mma_tf32(acc[1][nt], a0[1], a1[1], a2[1], a3[1], b0, b1);
            }
        }
        __syncthreads();
        if (it + 2 < DEC_TILES) { issue(it + 2, s); cp_commit(); }
    }
    const float* bb = &bd2[ncol0];
    #pragma unroll
    for (int mi = 0; mi < 2; mi++)
        #pragma unroll
        for (int nt = 0; nt < 4; nt++) {
            int m = m0w + mi * 16 + gid;
            int nn = nbw + nt * 8 + tid4 * 2;
            float bv0 = bb[nn], bv1 = bb[nn + 1];
            float v0 = acc[mi][nt][0] + bv0, v1 = acc[mi][nt][1] + bv1;
            float v2 = acc[mi][nt][2] + bv0, v3 = acc[mi][nt][3] + bv1;
            float2 r0 = make_float2(1.f / (1.f + __expf(-v0)), 1.f / (1.f + __expf(-v1)));
            float2 r1 = make_float2(1.f / (1.f + __expf(-v2)), 1.f / (1.f + __expf(-v3)));
            *(float2*)&out[m * IND + ncol0 + nn]       = r0;
            *(float2*)&out[(m + 8) * IND + ncol0 + nn] = r1;
        }
}

// ---------------- launch -----------------------------------------------------
extern "C" void kernel_launch(void* const* d_in, const int* in_sizes, int n_in,
                              void* d_out, int out_size) {
    const float* x      = (const float*)d_in[0];
    const int*   ei     = (const int*)d_in[1];
    const float* eps    = (const float*)d_in[2];
    const float* Wmsg   = (const float*)d_in[3];
    const float* bmsg   = (const float*)d_in[4];
    const float* We1    = (const float*)d_in[5];
    const float* be1    = (const float*)d_in[6];
    const float* Wmean  = (const float*)d_in[7];
    const float* bmean  = (const float*)d_in[8];
    const float* Wlv    = (const float*)d_in[9];
    const float* blv    = (const float*)d_in[10];
    const float* Wd1    = (const float*)d_in[11];
    const float* bd1    = (const float*)d_in[12];
    const float* Wd2    = (const float*)d_in[13];
    const float* bd2    = (const float*)d_in[14];

    float* out      = (float*)d_out;
    float* out_xhat = out;
    float* out_mean = out + (size_t)B_ * IND;
    float* out_lv   = out_mean + B_ * L_;

    k_count_cvt<<<2000, 256>>>(ei, x);                       // 0
    k_fill_scan<<<32, 1024>>>(ei);                           // 1
    k_conv<<<N_, 256>>>(x, Wmsg, bmsg);                      // 2
    k_gemm_enc<<<dim3(4, ENC_KBLK), 256>>>(We1);             // 3  <- ncu capture slot
    k_mid<<<B_, 512>>>(be1, Wmean, bmean, Wlv, blv, eps, Wd1, bd1, out_mean, out_lv); // 4
    k_gemm_dec<<<500, 256>>>(Wd2, bd2, out_xhat);            // 5
}

// round 11
// speedup vs baseline: 2.3809x; 1.1127x over previous
#include <cuda_runtime.h>
#include <cuda_bf16.h>

#define B_   64
#define N_   1000
#define F_   64
#define E_   32000
#define IND  64000
#define HID  512
#define L_   128
#define ENC_KBLK 100
#define ENC_TILES 40     // 640 / 16
#define DEC_TILES 32     // 512 / 16

// ---------------- scratch ----------------------------------------------------
__device__ int   g_deg[N_];          // zero-init; reset by k_conv after use
__device__ int   g_fill[N_];
__device__ int   g_rowptr[N_ + 1];
__device__ int   g_col[E_];
__device__ uint4 g_xb4[B_ * IND / 8];
__device__ float g_xs[B_ * IND];
__device__ float g_part[ENC_KBLK * B_ * HID];
__device__ float g_hd[B_ * HID];

// ---------------- helpers ----------------------------------------------------
__device__ __forceinline__ unsigned f2tf32(float f) {
    unsigned r;
    asm("cvt.rna.tf32.f32 %0, %1;" : "=r"(r) : "f"(f));
    return r;
}
__device__ __forceinline__ float tf32r(float f) {
    return __uint_as_float(f2tf32(f));
}

__device__ __forceinline__ void mma_tf32(float c[4],
                                         unsigned a0, unsigned a1, unsigned a2, unsigned a3,
                                         unsigned b0, unsigned b1) {
    asm volatile(
        "mma.sync.aligned.m16n8k8.row.col.f32.tf32.tf32.f32 "
        "{%0,%1,%2,%3}, {%4,%5,%6,%7}, {%8,%9}, {%0,%1,%2,%3};"
        : "+f"(c[0]), "+f"(c[1]), "+f"(c[2]), "+f"(c[3])
        : "r"(a0), "r"(a1), "r"(a2), "r"(a3), "r"(b0), "r"(b1));
}

__device__ __forceinline__ void cp16(void* dst, const void* src) {
    unsigned d = (unsigned)__cvta_generic_to_shared(dst);
    asm volatile("cp.async.cg.shared.global [%0], [%1], 16;" :: "r"(d), "l"(src));
}
__device__ __forceinline__ void cp_commit() { asm volatile("cp.async.commit_group;"); }
__device__ __forceinline__ void cp_wait2()  { asm volatile("cp.async.wait_group 2;"); }

// A: [64][16] rows, swizzle keeps 16B cp.async alignment, conflict-free frags
#define ASW2(m, c) ((c) ^ ((((m) >> 1) & 3) * 4))
// B: [16][128] rows
#define BSW(k, c)  ((c) ^ (((k) & 3) * 8))

__device__ __forceinline__ unsigned packbf(float lo, float hi) {
    __nv_bfloat162 h = __float22bfloat162_rn(make_float2(lo, hi));
    return *reinterpret_cast<unsigned*>(&h);
}
__device__ __forceinline__ void acc8(float* a, uint4 v) {
    unsigned u;
    u = v.x; a[0] += __uint_as_float(u << 16); a[1] += __uint_as_float(u & 0xffff0000u);
    u = v.y; a[2] += __uint_as_float(u << 16); a[3] += __uint_as_float(u & 0xffff0000u);
    u = v.z; a[4] += __uint_as_float(u << 16); a[5] += __uint_as_float(u & 0xffff0000u);
    u = v.w; a[6] += __uint_as_float(u << 16); a[7] += __uint_as_float(u & 0xffff0000u);
}

// ---------------- count + x->bf16 convert (fused) -----------------------------
// grid 2000 x 256 = 512000 threads = B*IND/8 EXACTLY
__global__ void __launch_bounds__(256) k_count_cvt(const int* __restrict__ ei,
                                                   const float* __restrict__ x) {
    int tid = blockIdx.x * 256 + threadIdx.x;
    const float4* xp = (const float4*)x + (size_t)tid * 2;
    float4 v0 = __ldg(xp), v1 = __ldg(xp + 1);
    g_xb4[tid] = make_uint4(packbf(v0.x, v0.y), packbf(v0.z, v0.w),
                            packbf(v1.x, v1.y), packbf(v1.z, v1.w));
    if (tid < E_) atomicAdd(&g_deg[ei[E_ + tid]], 1);
}

// ---------------- fill with per-block redundant scan --------------------------
__global__ void __launch_bounds__(1024) k_fill_scan(const int* __restrict__ ei) {
    __shared__ int hist[1024];
    __shared__ int rp[1024];
    int t = threadIdx.x;
    int d0 = (t < N_) ? g_deg[t] : 0;
    hist[t] = d0;
    rp[t] = d0;
    __syncthreads();
    for (int off = 1; off < 1024; off <<= 1) {
        int v = (t >= off) ? rp[t - off] : 0;
        __syncthreads();
        rp[t] += v;
        __syncthreads();
    }
    if (blockIdx.x == 0) {
        if (t < N_) g_rowptr[t + 1] = rp[t];
        if (t == 0) g_rowptr[0] = 0;
    }
    if (t < 1000) {
        int e = blockIdx.x * 1000 + t;
        int d = ei[E_ + e];
        int p = atomicAdd(&g_fill[d], 1);
        g_col[(rp[d] - hist[d]) + p] = ei[e];
    }
}

// ---------------- fused GeneralConv: bf16 gather + tf32-MMA epilogue ---------
__global__ void __launch_bounds__(256, 4) k_conv(const float* __restrict__ x,
                                                 const float* __restrict__ Wm,
                                                 const float* __restrict__ bm) {
    __shared__ float Wsh[64][72];
    __shared__ float accsh[64][68];
    __shared__ int   adjsh[256];
    const int n = blockIdx.x;
    const int t = threadIdx.x;
    const int oct = t & 7, g = t >> 3;

    for (int i = t; i < 4096; i += 256)
        Wsh[i >> 6][i & 63] = Wm[i];

    const int r0 = g_rowptr[n], r1 = g_rowptr[n + 1];
    const int deg = r1 - r0;
    const float inv = 1.f / fmaxf((float)deg, 1.f);

    float acc[2][8];
    #pragma unroll
    for (int i = 0; i < 2; i++)
        #pragma unroll
        for (int k = 0; k < 8; k++) acc[i][k] = 0.f;

    const uint4* xq = g_xb4 + (size_t)(g * 2) * 8000 + oct;
    for (int base = r0; base < r1; base += 256) {
        int cnt = min(256, r1 - base);
        __syncthreads();
        if (t < cnt) adjsh[t] = g_col[base + t];
        __syncthreads();
        for (int j = 0; j < cnt; ++j) {
            const uint4* p = xq + adjsh[j] * 8;
            acc8(acc[0], __ldg(p));
            acc8(acc[1], __ldg(p + 8000));
        }
    }
    if (t == 0) { g_deg[n] = 0; g_fill[n] = 0; }
    __syncthreads();
    #pragma unroll
    for (int i = 0; i < 2; i++)
        #pragma unroll
        for (int k = 0; k < 8; k++) accsh[g * 2 + i][oct * 8 + k] = acc[i][k];
    __syncthreads();

    const int warp = t >> 5, lane = t & 31;
    const int gid = lane >> 2, tid4 = lane & 3;
    const int m0 = (warp & 3) * 16;
    const int n0 = (warp >> 2) * 32;

    float c[4][4];
    #pragma unroll
    for (int i = 0; i < 4; i++)
        #pragma unroll
        for (int j = 0; j < 4; j++) c[i][j] = 0.f;

    #pragma unroll
    for (int kk = 0; kk < 64; kk += 8) {
        unsigned a0 = f2tf32(accsh[m0 + gid][kk + tid4]);
        unsigned a1 = f2tf32(accsh[m0 + gid + 8][kk + tid4]);
        unsigned a2 = f2tf32(accsh[m0 + gid][kk + tid4 + 4]);
        unsigned a3 = f2tf32(accsh[m0 + gid + 8][kk + tid4 + 4]);
        #pragma unroll
        for (int nt = 0; nt < 4; nt++) {
            int nn = n0 + nt * 8 + gid;
            unsigned b0 = f2tf32(Wsh[kk + tid4][nn]);
            unsigned b1 = f2tf32(Wsh[kk + tid4 + 4][nn]);
            mma_tf32(c[nt], a0, a1, a2, a3, b0, b1);
        }
    }

    #pragma unroll
    for (int nt = 0; nt < 4; nt++) {
        const int f0 = n0 + nt * 8 + tid4 * 2;
        float bv0 = 0.f, bv1 = 0.f;
        if (deg > 0) { bv0 = bm[f0]; bv1 = bm[f0 + 1]; }
        #pragma unroll
        for (int half = 0; half < 2; half++) {
            const int b = m0 + gid + half * 8;
            const float2 xr = *(const float2*)&x[((size_t)b * N_ + n) * 64 + f0];
            float h0 = c[nt][half * 2 + 0] * inv + bv0 + xr.x;
            float h1 = c[nt][half * 2 + 1] * inv + bv1 + xr.y;
            h0 = (h0 >= 0.f) ? h0 : 0.01f * h0;
            h1 = (h1 >= 0.f) ? h1 : 0.01f * h1;
            h0 = tf32r(h0); h1 = tf32r(h1);
            *(float2*)&g_xs[(size_t)b * IND + n * 64 + f0] = make_float2(h0, h1);
        }
    }
}

// ---------------- encoder GEMM: 4-stage cp.async, K=16/stage -----------------
__global__ void __launch_bounds__(256) k_gemm_enc(const float* __restrict__ W) {
    __shared__ float As[4][64][16];      // 16 KB
    __shared__ float Bs[4][16][128];     // 32 KB
    const int nblk = blockIdx.x;
    const int kblk = blockIdx.y;
    const int t = threadIdx.x;
    const int lane = t & 31, warp = t >> 5;
    const int gid = lane >> 2, tid4 = lane & 3;
    const int m0w = (warp & 1) * 32, nbw = (warp >> 1) * 32;
    const int la_m = t >> 2, la_k = (t & 3) * 4;
    const int lb_k = t >> 4, lb_c = (t & 15) * 8;
    const int kbase0 = kblk * 640;
    const int ncol0 = nblk * 128;

    float acc[2][4][4];
    #pragma unroll
    for (int a = 0; a < 2; a++)
        #pragma unroll
        for (int i = 0; i < 4; i++)
            #pragma unroll
            for (int j = 0; j < 4; j++) acc[a][i][j] = 0.f;

    auto issue = [&](int it, int buf) {
        const float* ag = &g_xs[la_m * IND + kbase0 + it * 16 + la_k];
        cp16(&As[buf][la_m][ASW2(la_m, la_k)], ag);
        const float* bg = &W[(kbase0 + it * 16 + lb_k) * HID + ncol0 + lb_c];
        cp16(&Bs[buf][lb_k][BSW(lb_k, lb_c)], bg);
        cp16(&Bs[buf][lb_k][BSW(lb_k, lb_c + 4)], bg + 4);
    };

    issue(0, 0); cp_commit();
    issue(1, 1); cp_commit();
    issue(2, 2); cp_commit();

    for (int it = 0; it < ENC_TILES; ++it) {
        cp_wait2();
        __syncthreads();
        if (it + 3 < ENC_TILES) issue(it + 3, (it + 3) & 3);
        cp_commit();
        const int s = it & 3;
        #pragma unroll
        for (int kk = 0; kk < 16; kk += 8) {
            unsigned a0[2], a1[2], a2[2], a3[2];
            #pragma unroll
            for (int mi = 0; mi < 2; mi++) {
                int mr = m0w + mi * 16 + gid;
                a0[mi] = __float_as_uint(As[s][mr][ASW2(mr, kk + tid4)]);
                a1[mi] = __float_as_uint(As[s][mr + 8][ASW2(mr + 8, kk + tid4)]);
                a2[mi] = __float_as_uint(As[s][mr][ASW2(mr, kk + tid4 + 4)]);
                a3[mi] = __float_as_uint(As[s][mr + 8][ASW2(mr + 8, kk + tid4 + 4)]);
            }
            #pragma unroll
            for (int nt = 0; nt < 4; nt++) {
                int nn = nbw + nt * 8 + gid;
                unsigned b0 = __float_as_uint(Bs[s][kk + tid4][BSW(kk + tid4, nn)]);
                unsigned b1 = __float_as_uint(Bs[s][kk + tid4 + 4][BSW(kk + tid4 + 4, nn)]);
                mma_tf32(acc[0][nt], a0[0], a1[0], a2[0], a3[0], b0, b1);
                mma_tf32(acc[1][nt], a0[1], a1[1], a2[1], a3[1], b0, b1);
            }
        }
    }
    float* P = g_part + kblk * (B_ * HID) + ncol0;
    #pragma unroll
    for (int mi = 0; mi < 2; mi++)
        #pragma unroll
        for (int nt = 0; nt < 4; nt++) {
            int m = m0w + mi * 16 + gid;
            int nn = nbw + nt * 8 + tid4 * 2;
            *(float2*)&P[m * HID + nn]       = make_float2(acc[mi][nt][0], acc[mi][nt][1]);
            *(float2*)&P[(m + 8) * HID + nn] = make_float2(acc[mi][nt][2], acc[mi][nt][3]);
        }
}

// ---------------- fused: split-K reduce + bias/relu + mean/lv/z + hd ---------
__global__ void __launch_bounds__(512) k_mid(const float* __restrict__ be1,
                                             const float* __restrict__ Wmean,
                                             const float* __restrict__ bmean,
                                             const float* __restrict__ Wlv,
                                             const float* __restrict__ blv,
                                             const float* __restrict__ eps,
                                             const float* __restrict__ Wd1,
                                             const float* __restrict__ bd1,
                                             float* __restrict__ out_mean,
                                             float* __restrict__ out_lv) {
    __shared__ float hesh[HID];
    __shared__ float mpart[4][L_], vpart[4][L_];
    __shared__ float zsh[L_];
    int b = blockIdx.x, t = threadIdx.x;
    {
        float s = 0.f;
        const float* P = g_part + b * HID + t;
        #pragma unroll 5
        for (int kb = 0; kb < ENC_KBLK; kb++) s += P[kb * (B_ * HID)];
        hesh[t] = fmaxf(s + be1[t], 0.f);
    }
    __syncthreads();
    int l = t & 127, kq = t >> 7;
    float m = 0.f, v = 0.f;
    #pragma unroll 8
    for (int k = kq * 128; k < (kq + 1) * 128; ++k) {
        float h = hesh[k];
        m += h * Wmean[k * L_ + l];
        v += h * Wlv[k * L_ + l];
    }
    mpart[kq][l] = m; vpart[kq][l] = v;
    __syncthreads();
    if (t < L_) {
        m = mpart[0][t] + mpart[1][t] + mpart[2][t] + mpart[3][t] + bmean[t];
        v = vpart[0][t] + vpart[1][t] + vpart[2][t] + vpart[3][t] + blv[t];
        out_mean[b * L_ + t] = m;
        out_lv[b * L_ + t]   = v;
        zsh[t] = m + expf(0.5f * v) * eps[b * L_ + t];
    }
    __syncthreads();
    float a = 0.f;
    #pragma unroll 8
    for (int k = 0; k < L_; ++k) a += zsh[k] * Wd1[k * HID + t];
    g_hd[b * HID + t] = tf32r(fmaxf(a + bd1[t], 0.f));
}

// ---------------- decoder GEMM: 4-stage cp.async, K=16/stage -----------------
__global__ void __launch_bounds__(256) k_gemm_dec(const float* __restrict__ W,
                                                  const float* __restrict__ bd2,
                                                  float* __restrict__ out) {
    __shared__ float As[4][64][16];
    __shared__ float Bs[4][16][128];
    const int nblk = blockIdx.x;
    const int t = threadIdx.x;
    const int lane = t & 31, warp = t >> 5;
    const int gid = lane >> 2, tid4 = lane & 3;
    const int m0w = (warp & 1) * 32, nbw = (warp >> 1) * 32;
    const int la_m = t >> 2, la_k = (t & 3) * 4;
    const int lb_k = t >> 4, lb_c = (t & 15) * 8;
    const int ncol0 = nblk * 128;

    float acc[2][4][4];
    #pragma unroll
    for (int a = 0; a < 2; a++)
        #pragma unroll
        for (int i = 0; i < 4; i++)
            #pragma unroll
            for (int j = 0; j < 4; j++) acc[a][i][j] = 0.f;

    auto issue = [&](int it, int buf) {
        const float* ag = &g_hd[la_m * HID + it * 16 + la_k];
        cp16(&As[buf][la_m][ASW2(la_m, la_k)], ag);
        const float* bg = &W[(it * 16 + lb_k) * IND + ncol0 + lb_c];
        cp16(&Bs[buf][lb_k][BSW(lb_k, lb_c)], bg);
        cp16(&Bs[buf][lb_k][BSW(lb_k, lb_c + 4)], bg + 4);
    };

    issue(0, 0); cp_commit();
    issue(1, 1); cp_commit();
    issue(2, 2); cp_commit();

    for (int it = 0; it < DEC_TILES; ++it) {
        cp_wait2();
        __syncthreads();
        if (it + 3 < DEC_TILES) issue(it + 3, (it + 3) & 3);
        cp_commit();
        const int s = it & 3;
        #pragma unroll
        for (int kk = 0; kk < 16; kk += 8) {
            unsigned a0[2], a1[2], a2[2], a3[2];
            #pragma unroll
            for (int mi = 0; mi < 2; mi++) {
                int mr = m0w + mi * 16 + gid;
                a0[mi] = __float_as_uint(As[s][mr][ASW2(mr, kk + tid4)]);
                a1[mi] = __float_as_uint(As[s][mr + 8][ASW2(mr + 8, kk + tid4)]);
                a2[mi] = __float_as_uint(As[s][mr][ASW2(mr, kk + tid4 + 4)]);
                a3[mi] = __float_as_uint(As[s][mr + 8][ASW2(mr + 8, kk + tid4 + 4)]);
            }
            #pragma unroll
            for (int nt = 0; nt < 4; nt++) {
                int nn = nbw + nt * 8 + gid;
                unsigned b0 = __float_as_uint(Bs[s][kk + tid4][BSW(kk + tid4, nn)]);
                unsigned b1 = __float_as_uint(Bs[s][kk + tid4 + 4][BSW(kk + tid4 + 4, nn)]);
                mma_tf32(acc[0][nt], a0[0], a1[0], a2[0], a3[0], b0, b1);
                mma_tf32(acc[1][nt], a0[1], a1[1], a2[1], a3[1], b0, b1);
            }
        }
    }
    const float* bb = &bd2[ncol0];
    #pragma unroll
    for (int mi = 0; mi < 2; mi++)
        #pragma unroll
        for (int nt = 0; nt < 4; nt++) {
            int m = m0w + mi * 16 + gid;
            int nn = nbw + nt * 8 + tid4 * 2;
            float bv0 = bb[nn], bv1 = bb[nn + 1];
            float v0 = acc[mi][nt][0] + bv0, v1 = acc[mi][nt][1] + bv1;
            float v2 = acc[mi][nt][2] + bv0, v3 = acc[mi][nt][3] + bv1;
            float2 r0 = make_float2(1.f / (1.f + __expf(-v0)), 1.f / (1.f + __expf(-v1)));
            float2 r1 = make_float2(1.f / (1.f + __expf(-v2)), 1.f / (1.f + __expf(-v3)));
            *(float2*)&out[m * IND + ncol0 + nn]       = r0;
            *(float2*)&out[(m + 8) * IND + ncol0 + nn] = r1;
        }
}

// ---------------- launch -----------------------------------------------------
extern "C" void kernel_launch(void* const* d_in, const int* in_sizes, int n_in,
                              void* d_out, int out_size) {
    const float* x      = (const float*)d_in[0];
    const int*   ei     = (const int*)d_in[1];
    const float* eps    = (const float*)d_in[2];
    const float* Wmsg   = (const float*)d_in[3];
    const float* bmsg   = (const float*)d_in[4];
    const float* We1    = (const float*)d_in[5];
    const float* be1    = (const float*)d_in[6];
    const float* Wmean  = (const float*)d_in[7];
    const float* bmean  = (const float*)d_in[8];
    const float* Wlv    = (const float*)d_in[9];
    const float* blv    = (const float*)d_in[10];
    const float* Wd1    = (const float*)d_in[11];
    const float* bd1    = (const float*)d_in[12];
    const float* Wd2    = (const float*)d_in[13];
    const float* bd2    = (const float*)d_in[14];

    float* out      = (float*)d_out;
    float* out_xhat = out;
    float* out_mean = out + (size_t)B_ * IND;
    float* out_lv   = out_mean + B_ * L_;

    k_count_cvt<<<2000, 256>>>(ei, x);                       // 0
    k_fill_scan<<<32, 1024>>>(ei);                           // 1
    k_conv<<<N_, 256>>>(x, Wmsg, bmsg);                      // 2
    k_gemm_enc<<<dim3(4, ENC_KBLK), 256>>>(We1);             // 3  <- ncu capture slot
    k_mid<<<B_, 512>>>(be1, Wmean, bmean, Wlv, blv, eps, Wd1, bd1, out_mean, out_lv); // 4
    k_gemm_dec<<<500, 256>>>(Wd2, bd2, out_xhat);            // 5
}